// round 4
// baseline (speedup 1.0000x reference)
#include <cuda_runtime.h>

// ---------------------------------------------------------------------------
// Problem constants
// ---------------------------------------------------------------------------
#define BATCH 16
#define TLEN  4096
#define NTOK  (BATCH * TLEN)   // 65536 tokens
#define DDIM  512
#define EDIM  256
#define NCODE 1024

// Output packing: z_out | commitment[16] | codebook[16] | code[65536]
#define N_ZOUT   ((size_t)NTOK * DDIM)
#define OFF_L1   (N_ZOUT)
#define OFF_L2   (N_ZOUT + 16)
#define OFF_CODE (N_ZOUT + 32)
#define OUT_FULL (N_ZOUT + 32 + NTOK)

// LPT split: 888 tiles of 64 tokens (=296 slots x 3 exact waves), then 544 of 16
#define MAIN_TILES 888
#define MAIN_TOKENS (MAIN_TILES * 64)   // 56832
#define TAIL_TILES ((NTOK - MAIN_TOKENS) / 16)  // 544

typedef unsigned long long u64;

__device__ __forceinline__ float2 unpack2(u64 v) {
    float2 r; asm("mov.b64 {%0, %1}, %2;" : "=f"(r.x), "=f"(r.y) : "l"(v)); return r;
}
__device__ __forceinline__ void fma2(u64& d, u64 a, u64 b) {
    asm("fma.rn.f32x2 %0, %1, %2, %0;" : "+l"(d) : "l"(a), "l"(b));
}

// ---------------------------------------------------------------------------
// Device scratch
// ---------------------------------------------------------------------------
__device__ float g_wdT2[DDIM / 2 * EDIM * 2];   // [k-pair p][e][2]: wd[e][2p], wd[e][2p+1]
__device__ float g_cbT2[EDIM / 2 * NCODE * 2];  // [e-pair p][j][2]: cb[j][2p], cb[j][2p+1]
__device__ float g_cnh[NCODE];                  // 0.5*||c_j||^2
__device__ float g_M[NCODE * DDIM];             // codebook @ w_up^T
__device__ float g_partial16[NTOK / 16];        // per-16-token loss sums (4096)

// ---------------------------------------------------------------------------
// Prep kernels
// ---------------------------------------------------------------------------
__global__ void k_prep_wdT2(const float* __restrict__ wd) {
    int idx = blockIdx.x * 256 + threadIdx.x;    // 131072
    int s = idx & 1, e = (idx >> 1) & 255, p = idx >> 9;
    g_wdT2[idx] = wd[e * DDIM + 2 * p + s];
}

__global__ void k_prep_cbT2(const float* __restrict__ cb) {
    int idx = blockIdx.x * 256 + threadIdx.x;    // 262144
    int s = idx & 1, j = (idx >> 1) & 1023, p = idx >> 11;
    g_cbT2[idx] = cb[j * EDIM + 2 * p + s];
}

__global__ void k_prep_cnh(const float* __restrict__ cb) {
    int j = blockIdx.x * 256 + threadIdx.x;
    if (j < NCODE) {
        const float4* r = (const float4*)(cb + (size_t)j * EDIM);
        float s = 0.f;
#pragma unroll 8
        for (int q = 0; q < EDIM / 4; q++) {
            float4 v = r[q];
            s += v.x * v.x + v.y * v.y + v.z * v.z + v.w * v.w;
        }
        g_cnh[j] = 0.5f * s;
    }
}

// M[j][d] = sum_e cb[j][e] * w_up[d][e]
__global__ void k_prep_M(const float* __restrict__ cb, const float* __restrict__ wu) {
    __shared__ float scb[8 * 256];
    __shared__ float swuT[256][33];
    int tid = threadIdx.x;
    int j0 = (blockIdx.x >> 4) * 8;
    int d0 = (blockIdx.x & 15) * 32;
#pragma unroll
    for (int r = 0; r < 2; r++) {
        int idx = tid + r * 256;
        int row = idx >> 6, q = (idx & 63) << 2;
        *(float4*)&scb[row * 256 + q] = *(const float4*)&cb[(size_t)(j0 + row) * EDIM + q];
    }
#pragma unroll
    for (int r = 0; r < 8; r++) {
        int idx = tid + r * 256;
        int row = idx >> 6, q = (idx & 63) << 2;
        float4 v = *(const float4*)&wu[(size_t)(d0 + row) * EDIM + q];
        swuT[q + 0][row] = v.x; swuT[q + 1][row] = v.y;
        swuT[q + 2][row] = v.z; swuT[q + 3][row] = v.w;
    }
    __syncthreads();
    int jl = tid >> 5, dl = tid & 31;
    float s = 0.f;
#pragma unroll 8
    for (int e = 0; e < 256; e++) s += scb[jl * 256 + e] * swuT[e][dl];
    g_M[(size_t)(j0 + jl) * DDIM + d0 + dl] = s;
}

// ---------------------------------------------------------------------------
// Main fused tile kernel. BM tokens per CTA, BM*4 threads, warps = BM/8.
// Thread tile: 8 tokens x 4 columns, k-packed f32x2 accumulators (acc = 32 u64).
// Column map (within 128-col group): {tx*2, tx*2+1, 64+tx*2, 64+tx*2+1}.
// smem: zesm[BM][256] | region{ zt[BM][32] + wsm[16][256]  OR  cbsm[32][256] }
// ---------------------------------------------------------------------------
template<int BM>
__global__ __launch_bounds__(BM * 4, (BM == 64) ? 2 : 4) void vq_tile(
    const float* __restrict__ z, const float* __restrict__ cb,
    float* __restrict__ out, int tok0base, int write_extra)
{
    extern __shared__ float sm[];
    float* zesm = sm;                         // BM*256 floats
    float* zt   = sm + BM * 256;              // BM*32
    float* wsm  = zt + BM * 32;               // 16*256 = 4096
    float* cbsm = sm + BM * 256;              // 32*256 = 8192 (overlaps zt+wsm)
    __shared__ int   scode[BM];
    __shared__ float sdist[BM];

    const int tid = threadIdx.x;
    const int nthr = BM * 4;
    const int tx = tid & 31, ty = tid >> 5;
    const int tok0 = tok0base + blockIdx.x * BM;

    u64 acc[8][4];

    // ================= Phase 1: z_e = z @ w_down^T (two 128-col halves) ======
#pragma unroll 1
    for (int hh = 0; hh < 2; hh++) {
#pragma unroll
        for (int i = 0; i < 8; i++)
#pragma unroll
            for (int c = 0; c < 4; c++) acc[i][c] = 0ULL;

#pragma unroll 1
        for (int kc = 0; kc < DDIM; kc += 32) {
            for (int idx = tid; idx < BM * 8; idx += nthr) {       // zt: BM x 32
                int t = idx >> 3, q = (idx & 7) << 2;
                *(float4*)&zt[t * 32 + q] =
                    *(const float4*)&z[(size_t)(tok0 + t) * DDIM + kc + q];
            }
            for (int idx = tid; idx < 1024; idx += nthr) {          // wsm: 16 kp x 256
                int row = idx >> 6, off = (idx & 63) << 2;
                *(float4*)&wsm[row * 256 + off] =
                    *(const float4*)&g_wdT2[(size_t)(kc / 2 + row) * 512 + hh * 256 + off];
            }
            __syncthreads();
#pragma unroll
            for (int kk2 = 0; kk2 < 8; kk2++) {
                ulonglong2 b00 = *(const ulonglong2*)&wsm[(kk2 * 2) * 256 + tx * 4];
                ulonglong2 b01 = *(const ulonglong2*)&wsm[(kk2 * 2) * 256 + 128 + tx * 4];
                ulonglong2 b10 = *(const ulonglong2*)&wsm[(kk2 * 2 + 1) * 256 + tx * 4];
                ulonglong2 b11 = *(const ulonglong2*)&wsm[(kk2 * 2 + 1) * 256 + 128 + tx * 4];
#pragma unroll
                for (int i = 0; i < 8; i++) {
                    ulonglong2 a2 = *(const ulonglong2*)&zt[(ty * 8 + i) * 32 + kk2 * 4];
                    fma2(acc[i][0], a2.x, b00.x); fma2(acc[i][1], a2.x, b00.y);
                    fma2(acc[i][2], a2.x, b01.x); fma2(acc[i][3], a2.x, b01.y);
                    fma2(acc[i][0], a2.y, b10.x); fma2(acc[i][1], a2.y, b10.y);
                    fma2(acc[i][2], a2.y, b11.x); fma2(acc[i][3], a2.y, b11.y);
                }
            }
            __syncthreads();
        }
#pragma unroll
        for (int i = 0; i < 8; i++)
#pragma unroll
            for (int c = 0; c < 4; c++) {
                float2 v = unpack2(acc[i][c]);
                int col = hh * 128 + (c >> 1) * 64 + tx * 2 + (c & 1);
                zesm[(ty * 8 + i) * 256 + col] = v.x + v.y;
            }
    }
    __syncthreads();

    // ================= Phase 2: nearest code over 8 chunks of 128 ============
    float minv[8]; int mini[8];
#pragma unroll
    for (int i = 0; i < 8; i++) { minv[i] = 3.4e38f; mini[i] = 0; }

#pragma unroll 1
    for (int jc = 0; jc < 8; jc++) {
#pragma unroll
        for (int i = 0; i < 8; i++)
#pragma unroll
            for (int c = 0; c < 4; c++) acc[i][c] = 0ULL;

#pragma unroll 1
        for (int ce = 0; ce < 4; ce++) {                  // 64-e chunks (32 pairs)
            for (int idx = tid; idx < 2048; idx += nthr) { // cbsm: 32 kp x 256
                int row = idx >> 6, off = (idx & 63) << 2;
                *(float4*)&cbsm[row * 256 + off] =
                    *(const float4*)&g_cbT2[(size_t)(ce * 32 + row) * 2048 + jc * 256 + off];
            }
            __syncthreads();
#pragma unroll
            for (int kk2 = 0; kk2 < 16; kk2++) {
                ulonglong2 b00 = *(const ulonglong2*)&cbsm[(kk2 * 2) * 256 + tx * 4];
                ulonglong2 b01 = *(const ulonglong2*)&cbsm[(kk2 * 2) * 256 + 128 + tx * 4];
                ulonglong2 b10 = *(const ulonglong2*)&cbsm[(kk2 * 2 + 1) * 256 + tx * 4];
                ulonglong2 b11 = *(const ulonglong2*)&cbsm[(kk2 * 2 + 1) * 256 + 128 + tx * 4];
#pragma unroll
                for (int i = 0; i < 8; i++) {
                    ulonglong2 a2 = *(const ulonglong2*)&zesm[(ty * 8 + i) * 256 + ce * 64 + kk2 * 4];
                    fma2(acc[i][0], a2.x, b00.x); fma2(acc[i][1], a2.x, b00.y);
                    fma2(acc[i][2], a2.x, b01.x); fma2(acc[i][3], a2.x, b01.y);
                    fma2(acc[i][0], a2.y, b10.x); fma2(acc[i][1], a2.y, b10.y);
                    fma2(acc[i][2], a2.y, b11.x); fma2(acc[i][3], a2.y, b11.y);
                }
            }
            __syncthreads();
        }
        int jj[4]; float cn[4];
#pragma unroll
        for (int c = 0; c < 4; c++) {
            jj[c] = jc * 128 + (c >> 1) * 64 + tx * 2 + (c & 1);
            cn[c] = g_cnh[jj[c]];
        }
#pragma unroll
        for (int i = 0; i < 8; i++)
#pragma unroll
            for (int c = 0; c < 4; c++) {                 // ascending j within thread
                float2 v = unpack2(acc[i][c]);
                float s = cn[c] - v.x - v.y;              // 0.5||c||^2 - z_e.c
                if (s < minv[i]) { minv[i] = s; mini[i] = jj[c]; }
            }
    }

    // warp argmin reduce (tie -> lower index)
#pragma unroll
    for (int i = 0; i < 8; i++) {
        float v = minv[i]; int id = mini[i];
#pragma unroll
        for (int off = 16; off > 0; off >>= 1) {
            float ov = __shfl_down_sync(0xffffffffu, v, off);
            int   oi = __shfl_down_sync(0xffffffffu, id, off);
            if (ov < v || (ov == v && oi < id)) { v = ov; id = oi; }
        }
        if (tx == 0) scode[ty * 8 + i] = id;
    }
    __syncthreads();

    // ================= Epilogue ==============================================
    for (int idx = tid; idx < BM * 128; idx += nthr) {     // z_out gather from M
        int t = idx >> 7, q = idx & 127;
        int c = scode[t];
        float4 v = *(const float4*)&g_M[(size_t)c * DDIM + q * 4];
        *(float4*)&out[(size_t)(tok0 + t) * DDIM + q * 4] = v;
    }

    {   // exact loss ||c - z_e||^2, 4 threads/token, reads rotated by t
        int t = tid >> 2, sub = tid & 3;
        int c = scode[t];
        const float* crow = cb + (size_t)c * EDIM;
        float ls = 0.f;
#pragma unroll 4
        for (int k = 0; k < 16; k++) {
            int q = sub * 16 + ((k + t) & 15);
            float4 cv = *(const float4*)&crow[q * 4];
            float4 zv = *(float4*)&zesm[t * 256 + q * 4];
            float d0 = cv.x - zv.x, d1 = cv.y - zv.y;
            float d2 = cv.z - zv.z, d3 = cv.w - zv.w;
            ls += d0 * d0 + d1 * d1 + d2 * d2 + d3 * d3;
        }
        ls += __shfl_xor_sync(0xffffffffu, ls, 1);
        ls += __shfl_xor_sync(0xffffffffu, ls, 2);
        if (sub == 0) sdist[t] = ls;
    }
    __syncthreads();
    if (tid < BM / 16) {                                  // per-16-token granules
        float s = 0.f;
#pragma unroll
        for (int r = 0; r < 16; r++) s += sdist[tid * 16 + r];
        g_partial16[(tok0 >> 4) + tid] = s;
    }
    if (write_extra && tid < BM)
        out[OFF_CODE + tok0 + tid] = (float)scode[tid];
}

__global__ void k_finalize(float* __restrict__ out) {
    int b = threadIdx.x;
    if (b < BATCH) {
        float s = 0.f;
        for (int g = 0; g < 256; g++) s += g_partial16[b * 256 + g];  // fixed order
        float loss = s * (1.0f / ((float)TLEN * (float)EDIM));
        out[OFF_L1 + b] = loss;
        out[OFF_L2 + b] = loss;
    }
}

// ---------------------------------------------------------------------------
extern "C" void kernel_launch(void* const* d_in, const int* in_sizes, int n_in,
                              void* d_out, int out_size) {
    const float* z  = (const float*)d_in[0];
    const float* cb = (const float*)d_in[1];
    const float* wd = (const float*)d_in[2];
    const float* wu = (const float*)d_in[3];
    float* out = (float*)d_out;

    int write_extra = ((size_t)out_size >= OUT_FULL) ? 1 : 0;

    cudaFuncSetAttribute(vq_tile<64>, cudaFuncAttributeMaxDynamicSharedMemorySize, 98304);
    cudaFuncSetAttribute(vq_tile<16>, cudaFuncAttributeMaxDynamicSharedMemorySize, 49152);

    k_prep_wdT2<<<512, 256>>>(wd);
    k_prep_cbT2<<<1024, 256>>>(cb);
    k_prep_cnh<<<4, 256>>>(cb);
    k_prep_M<<<2048, 256>>>(cb, wu);
    vq_tile<16><<<TAIL_TILES, 64, 49152>>>(z, cb, out, MAIN_TOKENS, write_extra);
    vq_tile<64><<<MAIN_TILES, 256, 98304>>>(z, cb, out, 0, write_extra);
    if (write_extra) k_finalize<<<1, 32>>>(out);
}

// round 5
// speedup vs baseline: 1.1414x; 1.1414x over previous
#include <cuda_runtime.h>

// ---------------------------------------------------------------------------
// Problem constants
// ---------------------------------------------------------------------------
#define BATCH 16
#define TLEN  4096
#define NTOK  (BATCH * TLEN)   // 65536 tokens
#define DDIM  512
#define EDIM  256
#define NCODE 1024

// Output packing: z_out | commitment[16] | codebook[16] | code[65536]
#define N_ZOUT   ((size_t)NTOK * DDIM)
#define OFF_L1   (N_ZOUT)
#define OFF_L2   (N_ZOUT + 16)
#define OFF_CODE (N_ZOUT + 32)
#define OUT_FULL (N_ZOUT + 32 + NTOK)

// Mixed grid: 888 tiles of 64 tokens (3 exact waves at 2 CTA/SM) + 544 of 16
#define MAIN_TILES 888
#define MAIN_TOKENS (MAIN_TILES * 64)           // 56832
#define TAIL_TILES ((NTOK - MAIN_TOKENS) / 16)  // 544
#define TOTAL_TILES (MAIN_TILES + TAIL_TILES)   // 1432

typedef unsigned long long u64;

__device__ __forceinline__ u64 pack2(float x, float y) {
    u64 r; asm("mov.b64 %0, {%1, %2};" : "=l"(r) : "f"(x), "f"(y)); return r;
}
__device__ __forceinline__ float2 unpack2(u64 v) {
    float2 r; asm("mov.b64 {%0, %1}, %2;" : "=f"(r.x), "=f"(r.y) : "l"(v)); return r;
}
__device__ __forceinline__ void fma2(u64& d, u64 a, u64 b) {
    asm("fma.rn.f32x2 %0, %1, %2, %0;" : "+l"(d) : "l"(a), "l"(b));
}

// ---------------------------------------------------------------------------
// Device scratch
// ---------------------------------------------------------------------------
__device__ float g_wdT[DDIM * EDIM];     // w_down transposed: [k][e]
__device__ float g_cbT[EDIM * NCODE];    // codebook transposed: [e][j]
__device__ float g_cnh[NCODE];           // 0.5*||c_j||^2
__device__ float g_M[NCODE * DDIM];      // codebook @ w_up^T
__device__ float g_partial16[NTOK / 16]; // per-16-token loss sums (4096)

// ---------------------------------------------------------------------------
// Fused small preps: wdT (512 blocks) | cbT (1024) | cnh (4)
// ---------------------------------------------------------------------------
__global__ void k_prep_small(const float* __restrict__ wd, const float* __restrict__ cb) {
    int b = blockIdx.x, tid = threadIdx.x;
    if (b < 512) {
        int idx = b * 256 + tid;
        int k = idx >> 8, e = idx & 255;
        g_wdT[idx] = wd[e * DDIM + k];
    } else if (b < 1536) {
        int idx = (b - 512) * 256 + tid;
        int e = idx >> 10, j = idx & 1023;
        g_cbT[idx] = cb[j * EDIM + e];
    } else {
        int j = (b - 1536) * 256 + tid;
        const float4* r = (const float4*)(cb + (size_t)j * EDIM);
        float s = 0.f;
#pragma unroll 8
        for (int q = 0; q < EDIM / 4; q++) {
            float4 v = r[q];
            s += v.x * v.x + v.y * v.y + v.z * v.z + v.w * v.w;
        }
        g_cnh[j] = 0.5f * s;
    }
}

// M[j][d] = sum_e cb[j][e]*wu[d][e].  8j x 32d per CTA, padded-row B layout
// (stride 260 floats -> 16B lane stride, conflict-free LDS.128).
__global__ void k_prep_M(const float* __restrict__ cb, const float* __restrict__ wu) {
    __shared__ float scb[8 * 256];
    __shared__ float swu[32 * 260];
    int tid = threadIdx.x;
    int j0 = (blockIdx.x >> 4) * 8;
    int d0 = (blockIdx.x & 15) * 32;
#pragma unroll
    for (int r = 0; r < 2; r++) {
        int idx = tid + r * 256;
        int row = idx >> 6, q = (idx & 63) << 2;
        *(float4*)&scb[row * 256 + q] = *(const float4*)&cb[(size_t)(j0 + row) * EDIM + q];
    }
#pragma unroll
    for (int r = 0; r < 8; r++) {
        int idx = tid + r * 256;
        int row = idx >> 6, q = (idx & 63) << 2;
        *(float4*)&swu[row * 260 + q] = *(const float4*)&wu[(size_t)(d0 + row) * EDIM + q];
    }
    __syncthreads();
    int jl = tid >> 5, dl = tid & 31;
    float s = 0.f;
#pragma unroll 16
    for (int e = 0; e < 256; e += 4) {
        float4 a = *(float4*)&scb[jl * 256 + e];
        float4 b = *(float4*)&swu[dl * 260 + e];
        s += a.x * b.x + a.y * b.y + a.z * b.z + a.w * b.w;
    }
    g_M[(size_t)(j0 + jl) * DDIM + d0 + dl] = s;
}

// ---------------------------------------------------------------------------
// Tile body (the R3 1090us structure), generalized over TI = tokens/thread.
// BM = 8*TI tokens per CTA, always 256 threads / 8 warps.
// Thread columns per 256-chunk: {tx*4..+3} and {128+tx*4..+3}.
// ---------------------------------------------------------------------------
template<int TI>
__device__ __forceinline__ void vq_body(
    const float* __restrict__ z, const float* __restrict__ cb,
    float* __restrict__ out, int tok0, int write_extra,
    float* sm, int* scode, float* sdist)
{
    constexpr int BM = TI * 8;
    float* zesm = sm;                    // BM*256
    float* zt   = sm + BM * 256;         // BM*32
    float* wsm  = zt + BM * 32;          // 32*256
    float* cbsm = sm + BM * 256;         // 32*256 (overlaps zt+wsm)

    const int tid = threadIdx.x;
    const int tx = tid & 31, ty = tid >> 5;

    u64 acc[TI][4];
#pragma unroll
    for (int i = 0; i < TI; i++)
#pragma unroll
        for (int g = 0; g < 4; g++) acc[i][g] = 0ULL;

    // ---------------- Phase 1: z_e = z @ w_down^T ----------------
#pragma unroll 1
    for (int kc = 0; kc < DDIM; kc += 32) {
        for (int idx = tid; idx < BM * 8; idx += 256) {
            int t = idx >> 3, q = (idx & 7) << 2;
            *(float4*)&zt[t * 32 + q] =
                *(const float4*)&z[(size_t)(tok0 + t) * DDIM + kc + q];
        }
#pragma unroll
        for (int r = 0; r < 8; r++) {
            int idx = tid + r * 256;
            int row = idx >> 6, q = (idx & 63) << 2;
            *(float4*)&wsm[row * 256 + q] = *(const float4*)&g_wdT[(size_t)(kc + row) * EDIM + q];
        }
        __syncthreads();
#pragma unroll
        for (int kk = 0; kk < 32; kk += 4) {
            float4 a4[TI];
#pragma unroll
            for (int i = 0; i < TI; i++)
                a4[i] = *(float4*)&zt[(ty * TI + i) * 32 + kk];
#pragma unroll
            for (int u = 0; u < 4; u++) {
                ulonglong2 b0 = *(const ulonglong2*)&wsm[(kk + u) * 256 + tx * 4];
                ulonglong2 b1 = *(const ulonglong2*)&wsm[(kk + u) * 256 + 128 + tx * 4];
#pragma unroll
                for (int i = 0; i < TI; i++) {
                    float av = (u == 0) ? a4[i].x : (u == 1) ? a4[i].y
                             : (u == 2) ? a4[i].z : a4[i].w;
                    u64 av2 = pack2(av, av);
                    fma2(acc[i][0], av2, b0.x); fma2(acc[i][1], av2, b0.y);
                    fma2(acc[i][2], av2, b1.x); fma2(acc[i][3], av2, b1.y);
                }
            }
        }
        __syncthreads();
    }
#pragma unroll
    for (int i = 0; i < TI; i++) {
        ulonglong2 s0; s0.x = acc[i][0]; s0.y = acc[i][1];
        ulonglong2 s1; s1.x = acc[i][2]; s1.y = acc[i][3];
        *(ulonglong2*)&zesm[(ty * TI + i) * 256 + tx * 4]       = s0;
        *(ulonglong2*)&zesm[(ty * TI + i) * 256 + 128 + tx * 4] = s1;
    }
    __syncthreads();

    // ---------------- Phase 2: nearest codebook entry ----------------
    float minv[TI]; int mini[TI];
#pragma unroll
    for (int i = 0; i < TI; i++) { minv[i] = 3.4e38f; mini[i] = 0; }

#pragma unroll 1
    for (int jc = 0; jc < 4; jc++) {
#pragma unroll
        for (int i = 0; i < TI; i++)
#pragma unroll
            for (int g = 0; g < 4; g++) acc[i][g] = 0ULL;

#pragma unroll 1
        for (int ec = 0; ec < EDIM; ec += 32) {
#pragma unroll
            for (int r = 0; r < 8; r++) {
                int idx = tid + r * 256;
                int row = idx >> 6, q = (idx & 63) << 2;
                *(float4*)&cbsm[row * 256 + q] =
                    *(const float4*)&g_cbT[(size_t)(ec + row) * NCODE + jc * 256 + q];
            }
            __syncthreads();
#pragma unroll
            for (int ee = 0; ee < 32; ee += 4) {
                float4 a4[TI];
#pragma unroll
                for (int i = 0; i < TI; i++)
                    a4[i] = *(float4*)&zesm[(ty * TI + i) * 256 + ec + ee];
#pragma unroll
                for (int u = 0; u < 4; u++) {
                    ulonglong2 b0 = *(const ulonglong2*)&cbsm[(ee + u) * 256 + tx * 4];
                    ulonglong2 b1 = *(const ulonglong2*)&cbsm[(ee + u) * 256 + 128 + tx * 4];
#pragma unroll
                    for (int i = 0; i < TI; i++) {
                        float av = (u == 0) ? a4[i].x : (u == 1) ? a4[i].y
                                 : (u == 2) ? a4[i].z : a4[i].w;
                        u64 av2 = pack2(av, av);
                        fma2(acc[i][0], av2, b0.x); fma2(acc[i][1], av2, b0.y);
                        fma2(acc[i][2], av2, b1.x); fma2(acc[i][3], av2, b1.y);
                    }
                }
            }
            __syncthreads();
        }
        int jb0 = jc * 256 + tx * 4;
        int jb1 = jc * 256 + 128 + tx * 4;
        float cn[8];
#pragma unroll
        for (int q = 0; q < 4; q++) { cn[q] = g_cnh[jb0 + q]; cn[4 + q] = g_cnh[jb1 + q]; }
#pragma unroll
        for (int i = 0; i < TI; i++) {
#pragma unroll
            for (int g = 0; g < 4; g++) {
                float2 s = unpack2(acc[i][g]);
                int jlo = (g < 2) ? (jb0 + (g & 1) * 2) : (jb1 + (g & 1) * 2);
                float c0 = cn[(g < 2 ? 0 : 4) + (g & 1) * 2];
                float c1 = cn[(g < 2 ? 0 : 4) + (g & 1) * 2 + 1];
                float d0 = c0 - s.x;                 // 0.5||c||^2 - z_e.c
                float d1 = c1 - s.y;
                if (d0 < minv[i]) { minv[i] = d0; mini[i] = jlo; }
                if (d1 < minv[i]) { minv[i] = d1; mini[i] = jlo + 1; }
            }
        }
    }

    // warp argmin reduce (tie -> lower index)
#pragma unroll
    for (int i = 0; i < TI; i++) {
        float v = minv[i]; int id = mini[i];
#pragma unroll
        for (int off = 16; off > 0; off >>= 1) {
            float ov = __shfl_down_sync(0xffffffffu, v, off);
            int   oi = __shfl_down_sync(0xffffffffu, id, off);
            if (ov < v || (ov == v && oi < id)) { v = ov; id = oi; }
        }
        if (tx == 0) scode[ty * TI + i] = id;
    }
    __syncthreads();

    // ---------------- Epilogue ----------------
    for (int idx = tid; idx < BM * 128; idx += 256) {
        int t = idx >> 7, q = idx & 127;
        int c = scode[t];
        float4 v = *(const float4*)&g_M[(size_t)c * DDIM + q * 4];
        *(float4*)&out[(size_t)(tok0 + t) * DDIM + q * 4] = v;
    }

    {   // exact loss ||c - z_e||^2, 4 threads per token (rotated reads)
        int t = tid >> 2, sub = tid & 3;
        if (t < BM) {
            int c = scode[t];
            const float* crow = cb + (size_t)c * EDIM;
            float ls = 0.f;
#pragma unroll 4
            for (int k = 0; k < 16; k++) {
                int q = sub * 16 + ((k + t) & 15);
                float4 cv = *(const float4*)&crow[q * 4];
                float4 zv = *(float4*)&zesm[t * 256 + q * 4];
                float d0 = cv.x - zv.x, d1 = cv.y - zv.y;
                float d2 = cv.z - zv.z, d3 = cv.w - zv.w;
                ls += d0 * d0 + d1 * d1 + d2 * d2 + d3 * d3;
            }
            ls += __shfl_xor_sync(0xffffffffu, ls, 1);
            ls += __shfl_xor_sync(0xffffffffu, ls, 2);
            if (sub == 0) sdist[t] = ls;
        }
    }
    __syncthreads();
    if (tid < BM / 16) {
        float s = 0.f;
#pragma unroll
        for (int r = 0; r < 16; r++) s += sdist[tid * 16 + r];
        g_partial16[(tok0 >> 4) + tid] = s;
    }
    if (write_extra && tid < BM)
        out[OFF_CODE + tok0 + tid] = (float)scode[tid];
}

// Mixed grid: blocks [0,888) -> 64-token tiles, [888,1432) -> 16-token tiles.
__global__ __launch_bounds__(256, 2) void vq_mixed(
    const float* __restrict__ z, const float* __restrict__ cb,
    float* __restrict__ out, int write_extra)
{
    extern __shared__ float sm[];
    __shared__ int   scode[64];
    __shared__ float sdist[64];
    if (blockIdx.x < MAIN_TILES)
        vq_body<8>(z, cb, out, blockIdx.x * 64, write_extra, sm, scode, sdist);
    else
        vq_body<2>(z, cb, out, MAIN_TOKENS + (blockIdx.x - MAIN_TILES) * 16,
                   write_extra, sm, scode, sdist);
}

__global__ void k_finalize(float* __restrict__ out) {
    int b = threadIdx.x;
    if (b < BATCH) {
        float s = 0.f;
        for (int g = 0; g < 256; g++) s += g_partial16[b * 256 + g];  // fixed order
        float loss = s * (1.0f / ((float)TLEN * (float)EDIM));
        out[OFF_L1 + b] = loss;
        out[OFF_L2 + b] = loss;
    }
}

// ---------------------------------------------------------------------------
extern "C" void kernel_launch(void* const* d_in, const int* in_sizes, int n_in,
                              void* d_out, int out_size) {
    const float* z  = (const float*)d_in[0];
    const float* cb = (const float*)d_in[1];
    const float* wd = (const float*)d_in[2];
    const float* wu = (const float*)d_in[3];
    float* out = (float*)d_out;

    int write_extra = ((size_t)out_size >= OUT_FULL) ? 1 : 0;

    cudaFuncSetAttribute(vq_mixed, cudaFuncAttributeMaxDynamicSharedMemorySize, 106496);

    k_prep_small<<<1540, 256>>>(wd, cb);
    k_prep_M<<<2048, 256>>>(cb, wu);
    vq_mixed<<<TOTAL_TILES, 256, 106496>>>(z, cb, out, write_extra);
    if (write_extra) k_finalize<<<1, 32>>>(out);
}

// round 11
// speedup vs baseline: 1.4115x; 1.2366x over previous
#include <cuda_runtime.h>
#include <cuda_bf16.h>
#include <cstdint>

// ---------------------------------------------------------------------------
// Problem constants
// ---------------------------------------------------------------------------
#define BATCH 16
#define TLEN  4096
#define NTOK  (BATCH * TLEN)   // 65536
#define DDIM  512
#define EDIM  256
#define NCODE 1024

#define N_ZOUT   ((size_t)NTOK * DDIM)
#define OFF_L1   (N_ZOUT)
#define OFF_L2   (N_ZOUT + 16)
#define OFF_CODE (N_ZOUT + 32)
#define OUT_FULL (N_ZOUT + 32 + NTOK)

#define TILE_M 128
#define NTILES (NTOK / TILE_M)   // 512
#define TAU 0.02f                // rescue threshold on half-score gap

typedef unsigned long long u64;
typedef unsigned int u32;

// ---------------------------------------------------------------------------
// Device scratch
// ---------------------------------------------------------------------------
__device__ __nv_bfloat16 g_wdhi[EDIM * DDIM];   // w_down [e][k] hi
__device__ __nv_bfloat16 g_wdlo[EDIM * DDIM];
__device__ __nv_bfloat16 g_cbhi[NCODE * EDIM];  // codebook [j][e] hi
__device__ __nv_bfloat16 g_cblo[NCODE * EDIM];
__device__ float g_cnh[NCODE];                  // 0.5*||c_j||^2
__device__ float g_M[NCODE * DDIM];             // codebook @ w_up^T
__device__ float g_lossTok[NTOK];
__device__ int   g_rescue[NTOK];
__device__ int   g_nrescue;

// ---------------------------------------------------------------------------
// mma / ldmatrix helpers (base-arch PTX, works on plain sm_103 target)
// ---------------------------------------------------------------------------
__device__ __forceinline__ u32 smem_u32(const void* p) {
    u32 a;
    asm("{ .reg .u64 t; cvta.to.shared.u64 t, %1; cvt.u32.u64 %0, t; }" : "=r"(a) : "l"(p));
    return a;
}

__device__ __forceinline__ void ldsm4(u32 addr, u32& r0, u32& r1, u32& r2, u32& r3) {
    asm volatile("ldmatrix.sync.aligned.m8n8.x4.shared.b16 {%0,%1,%2,%3}, [%4];"
                 : "=r"(r0), "=r"(r1), "=r"(r2), "=r"(r3) : "r"(addr));
}
__device__ __forceinline__ void ldsm2(u32 addr, u32& r0, u32& r1) {
    asm volatile("ldmatrix.sync.aligned.m8n8.x2.shared.b16 {%0,%1}, [%2];"
                 : "=r"(r0), "=r"(r1) : "r"(addr));
}
__device__ __forceinline__ void mma16816(float* c, const u32* a, const u32* b) {
    asm volatile(
        "mma.sync.aligned.m16n8k16.row.col.f32.bf16.bf16.f32 "
        "{%0,%1,%2,%3}, {%4,%5,%6,%7}, {%8,%9}, {%0,%1,%2,%3};"
        : "+f"(c[0]), "+f"(c[1]), "+f"(c[2]), "+f"(c[3])
        : "r"(a[0]), "r"(a[1]), "r"(a[2]), "r"(a[3]), "r"(b[0]), "r"(b[1]));
}

__device__ __forceinline__ u32 pack_hi(float a, float b) {
    __nv_bfloat162 t; t.x = __float2bfloat16(a); t.y = __float2bfloat16(b);
    return *(u32*)&t;
}
__device__ __forceinline__ u32 pack_lo(float a, float b) {
    __nv_bfloat162 t;
    t.x = __float2bfloat16(a - __bfloat162float(__float2bfloat16(a)));
    t.y = __float2bfloat16(b - __bfloat162float(__float2bfloat16(b)));
    return *(u32*)&t;
}

// ---------------------------------------------------------------------------
// Prep kernels
// ---------------------------------------------------------------------------
__global__ void k_prep_split(const float* __restrict__ wd, const float* __restrict__ cb) {
    int b = blockIdx.x, tid = threadIdx.x;
    if (b < 512) {
        int idx = b * 256 + tid;
        float v = wd[idx];
        __nv_bfloat16 hi = __float2bfloat16(v);
        g_wdhi[idx] = hi;
        g_wdlo[idx] = __float2bfloat16(v - __bfloat162float(hi));
    } else {
        int idx = (b - 512) * 256 + tid;
        float v = cb[idx];
        __nv_bfloat16 hi = __float2bfloat16(v);
        g_cbhi[idx] = hi;
        g_cblo[idx] = __float2bfloat16(v - __bfloat162float(hi));
    }
}

// IDENTICAL rounding to the R3 kernel's cnh (do not touch).
__global__ void k_prep_cnh(const float* __restrict__ cb) {
    int j = blockIdx.x * 256 + threadIdx.x;
    if (j == 0) g_nrescue = 0;
    if (j < NCODE) {
        const float4* r = (const float4*)(cb + (size_t)j * EDIM);
        float s = 0.f;
#pragma unroll 8
        for (int q = 0; q < EDIM / 4; q++) {
            float4 v = r[q];
            s += v.x * v.x + v.y * v.y + v.z * v.z + v.w * v.w;
        }
        g_cnh[j] = 0.5f * s;
    }
}

__global__ void k_prep_M(const float* __restrict__ cb, const float* __restrict__ wu) {
    __shared__ float scb[8 * 256];
    __shared__ float swu[32 * 260];
    int tid = threadIdx.x;
    int j0 = (blockIdx.x >> 4) * 8;
    int d0 = (blockIdx.x & 15) * 32;
#pragma unroll
    for (int r = 0; r < 2; r++) {
        int idx = tid + r * 256;
        int row = idx >> 6, q = (idx & 63) << 2;
        *(float4*)&scb[row * 256 + q] = *(const float4*)&cb[(size_t)(j0 + row) * EDIM + q];
    }
#pragma unroll
    for (int r = 0; r < 8; r++) {
        int idx = tid + r * 256;
        int row = idx >> 6, q = (idx & 63) << 2;
        *(float4*)&swu[row * 260 + q] = *(const float4*)&wu[(size_t)(d0 + row) * EDIM + q];
    }
    __syncthreads();
    int jl = tid >> 5, dl = tid & 31;
    float s = 0.f;
#pragma unroll 16
    for (int e = 0; e < 256; e += 4) {
        float4 a = *(float4*)&scb[jl * 256 + e];
        float4 b = *(float4*)&swu[dl * 260 + e];
        s += a.x * b.x + a.y * b.y + a.z * b.z + a.w * b.w;
    }
    g_M[(size_t)(j0 + jl) * DDIM + d0 + dl] = s;
}

// ---------------------------------------------------------------------------
// Main kernel: 128 tokens/CTA, 8 warps. bf16 hi/lo 3-term split via mma.sync.
// ---------------------------------------------------------------------------
#define OFF_ZEHI 0
#define OFF_ZELO 67584
#define OFF_P    135168
#define OFF_AZHI (OFF_P)
#define OFF_AZLO (OFF_P + 10240)
#define OFF_BWHI (OFF_P + 20480)
#define OFF_BWLO (OFF_P + 40960)
#define OFF_BHI  (OFF_P)
#define OFF_BLO  (OFF_P + 36864)
#define SM_TOTAL 208896

__global__ __launch_bounds__(256, 1) void vq_mma(
    const float* __restrict__ z, float* __restrict__ out, int write_extra)
{
    extern __shared__ char sm[];
    __shared__ float s_min[8][128];
    __shared__ float s_min2[8][128];
    __shared__ int   s_idx[8][128];
    __shared__ float s_zn[8][128];
    __shared__ int   s_code[128];

    const int tid = threadIdx.x;
    const int w = tid >> 5, lane = tid & 31;
    const int tok0 = blockIdx.x * TILE_M;
    const u32 smb = smem_u32(sm);

    float acc[8][4][4];
#pragma unroll
    for (int m = 0; m < 8; m++)
#pragma unroll
        for (int nt = 0; nt < 4; nt++)
#pragma unroll
            for (int c = 0; c < 4; c++) acc[m][nt][c] = 0.f;

    // ================= Phase 1: z_e = z @ w_down^T ===========================
#pragma unroll 1
    for (int kc = 0; kc < 16; kc++) {
#pragma unroll
        for (int j = 0; j < 4; j++) {
            int idx = tid + j * 256;
            int row = idx >> 3, c4 = idx & 7;
            float4 v = *(const float4*)&z[(size_t)(tok0 + row) * DDIM + kc * 32 + c4 * 4];
            u32 off = (u32)(row * 40 + c4 * 4) * 2;
            *(uint2*)(sm + OFF_AZHI + off) = make_uint2(pack_hi(v.x, v.y), pack_hi(v.z, v.w));
            *(uint2*)(sm + OFF_AZLO + off) = make_uint2(pack_lo(v.x, v.y), pack_lo(v.z, v.w));
        }
#pragma unroll
        for (int j = 0; j < 4; j++) {
            int idx = tid + j * 256;
            int row = idx >> 2, q = idx & 3;
            u32 doff = (u32)(row * 40 + q * 8) * 2;
            *(uint4*)(sm + OFF_BWHI + doff) = *(const uint4*)&g_wdhi[row * DDIM + kc * 32 + q * 8];
            *(uint4*)(sm + OFF_BWLO + doff) = *(const uint4*)&g_wdlo[row * DDIM + kc * 32 + q * 8];
        }
        __syncthreads();
#pragma unroll
        for (int ks = 0; ks < 2; ks++) {
            u32 bh[4][2], bl[4][2];
#pragma unroll
            for (int nt = 0; nt < 4; nt++) {
                u32 a = (u32)((w * 32 + nt * 8 + (lane & 7)) * 40 + ks * 16 + ((lane >> 3) & 1) * 8) * 2;
                ldsm2(smb + OFF_BWHI + a, bh[nt][0], bh[nt][1]);
                ldsm2(smb + OFF_BWLO + a, bl[nt][0], bl[nt][1]);
            }
#pragma unroll
            for (int m = 0; m < 8; m++) {
                u32 ah[4], al[4];
                u32 aA = (u32)((m * 16 + (lane & 15)) * 40 + ks * 16 + (lane >> 4) * 8) * 2;
                ldsm4(smb + OFF_AZHI + aA, ah[0], ah[1], ah[2], ah[3]);
                ldsm4(smb + OFF_AZLO + aA, al[0], al[1], al[2], al[3]);
#pragma unroll
                for (int nt = 0; nt < 4; nt++) {
                    mma16816(acc[m][nt], ah, bh[nt]);
                    mma16816(acc[m][nt], al, bh[nt]);
                    mma16816(acc[m][nt], ah, bl[nt]);
                }
            }
        }
        __syncthreads();
    }

    // ---- phase-1 epilogue: exact ||z_e||^2 partials + z_e hi/lo store ----
    {
        float znp[16];
#pragma unroll
        for (int s = 0; s < 16; s++) znp[s] = 0.f;
#pragma unroll
        for (int m = 0; m < 8; m++) {
#pragma unroll
            for (int nt = 0; nt < 4; nt++) {
                float c0 = acc[m][nt][0], c1 = acc[m][nt][1];
                float c2 = acc[m][nt][2], c3 = acc[m][nt][3];
                znp[m * 2]     += c0 * c0 + c1 * c1;
                znp[m * 2 + 1] += c2 * c2 + c3 * c3;
                int e0 = w * 32 + nt * 8 + 2 * (lane & 3);
                int r1 = m * 16 + (lane >> 2);
                u32 o1 = (u32)(r1 * 264 + e0) * 2;
                u32 o2 = (u32)((r1 + 8) * 264 + e0) * 2;
                *(u32*)(sm + OFF_ZEHI + o1) = pack_hi(c0, c1);
                *(u32*)(sm + OFF_ZELO + o1) = pack_lo(c0, c1);
                *(u32*)(sm + OFF_ZEHI + o2) = pack_hi(c2, c3);
                *(u32*)(sm + OFF_ZELO + o2) = pack_lo(c2, c3);
            }
        }
#pragma unroll
        for (int s = 0; s < 16; s++) {
            znp[s] += __shfl_xor_sync(0xffffffffu, znp[s], 1);
            znp[s] += __shfl_xor_sync(0xffffffffu, znp[s], 2);
        }
        if ((lane & 3) == 0) {
#pragma unroll
            for (int m = 0; m < 8; m++) {
                int r1 = m * 16 + (lane >> 2);
                s_zn[w][r1]     = znp[m * 2];
                s_zn[w][r1 + 8] = znp[m * 2 + 1];
            }
        }
    }
    __syncthreads();

    // ================= Phase 2: scores vs 1024 codes =========================
    float minv[16], minv2[16]; int mini[16];
#pragma unroll
    for (int s = 0; s < 16; s++) { minv[s] = 3.4e38f; minv2[s] = 3.4e38f; mini[s] = 0; }

#pragma unroll 1
    for (int jc = 0; jc < 4; jc++) {
#pragma unroll
        for (int m = 0; m < 8; m++)
#pragma unroll
            for (int nt = 0; nt < 4; nt++)
#pragma unroll
                for (int c = 0; c < 4; c++) acc[m][nt][c] = 0.f;

#pragma unroll 1
        for (int kc = 0; kc < 4; kc++) {
#pragma unroll
            for (int j = 0; j < 8; j++) {
                int idx = tid + j * 256;
                int row = idx >> 3, q = idx & 7;
                u32 doff = (u32)(row * 72 + q * 8) * 2;
                *(uint4*)(sm + OFF_BHI + doff) =
                    *(const uint4*)&g_cbhi[(size_t)(jc * 256 + row) * EDIM + kc * 64 + q * 8];
                *(uint4*)(sm + OFF_BLO + doff) =
                    *(const uint4*)&g_cblo[(size_t)(jc * 256 + row) * EDIM + kc * 64 + q * 8];
            }
            __syncthreads();
#pragma unroll
            for (int ks = 0; ks < 4; ks++) {
                u32 bh[4][2], bl[4][2];
#pragma unroll
                for (int nt = 0; nt < 4; nt++) {
                    u32 a = (u32)((w * 32 + nt * 8 + (lane & 7)) * 72 + ks * 16 + ((lane >> 3) & 1) * 8) * 2;
                    ldsm2(smb + OFF_BHI + a, bh[nt][0], bh[nt][1]);
                    ldsm2(smb + OFF_BLO + a, bl[nt][0], bl[nt][1]);
                }
#pragma unroll
                for (int m = 0; m < 8; m++) {
                    u32 ah[4], al[4];
                    u32 aA = (u32)((m * 16 + (lane & 15)) * 264 + kc * 64 + ks * 16 + (lane >> 4) * 8) * 2;
                    ldsm4(smb + OFF_ZEHI + aA, ah[0], ah[1], ah[2], ah[3]);
                    ldsm4(smb + OFF_ZELO + aA, al[0], al[1], al[2], al[3]);
#pragma unroll
                    for (int nt = 0; nt < 4; nt++) {
                        mma16816(acc[m][nt], ah, bh[nt]);
                        mma16816(acc[m][nt], al, bh[nt]);
                        mma16816(acc[m][nt], ah, bl[nt]);
                    }
                }
            }
            __syncthreads();
        }
        float cn[8];
#pragma unroll
        for (int nt = 0; nt < 4; nt++) {
            int jb = jc * 256 + w * 32 + nt * 8 + 2 * (lane & 3);
            cn[nt * 2]     = __ldg(&g_cnh[jb]);
            cn[nt * 2 + 1] = __ldg(&g_cnh[jb + 1]);
        }
#pragma unroll
        for (int m = 0; m < 8; m++) {
#pragma unroll
            for (int nt = 0; nt < 4; nt++) {
#pragma unroll
                for (int c = 0; c < 4; c++) {
                    float s = cn[nt * 2 + (c & 1)] - acc[m][nt][c];
                    int code = jc * 256 + w * 32 + nt * 8 + 2 * (lane & 3) + (c & 1);
                    int slot = m * 2 + (c >> 1);
                    if (s < minv[slot]) { minv2[slot] = minv[slot]; minv[slot] = s; mini[slot] = code; }
                    else if (s < minv2[slot]) { minv2[slot] = s; }
                }
            }
        }
    }

#pragma unroll
    for (int s = 0; s < 16; s++) {
#pragma unroll
        for (int off = 1; off <= 2; off <<= 1) {
            float ov  = __shfl_xor_sync(0xffffffffu, minv[s], off);
            float ov2 = __shfl_xor_sync(0xffffffffu, minv2[s], off);
            int   oi  = __shfl_xor_sync(0xffffffffu, mini[s], off);
            float nv2 = fminf(fmaxf(minv[s], ov), fminf(minv2[s], ov2));
            if (ov < minv[s] || (ov == minv[s] && oi < mini[s])) { minv[s] = ov; mini[s] = oi; }
            minv2[s] = nv2;
        }
    }
    if ((lane & 3) == 0) {
#pragma unroll
        for (int m = 0; m < 8; m++) {
            int r1 = m * 16 + (lane >> 2);
            s_min[w][r1] = minv[m * 2];      s_min2[w][r1] = minv2[m * 2];      s_idx[w][r1] = mini[m * 2];
            s_min[w][r1 + 8] = minv[m * 2 + 1]; s_min2[w][r1 + 8] = minv2[m * 2 + 1]; s_idx[w][r1 + 8] = mini[m * 2 + 1];
        }
    }
    __syncthreads();

    if (tid < 128) {
        float v = s_min[0][tid], v2 = s_min2[0][tid], zn = s_zn[0][tid];
        int id = s_idx[0][tid];
#pragma unroll
        for (int ww = 1; ww < 8; ww++) {
            float ov = s_min[ww][tid], ov2 = s_min2[ww][tid];
            int oi = s_idx[ww][tid];
            float nv2 = fminf(fmaxf(v, ov), fminf(v2, ov2));
            if (ov < v || (ov == v && oi < id)) { v = ov; id = oi; }
            v2 = nv2;
            zn += s_zn[ww][tid];
        }
        int tok = tok0 + tid;
        g_lossTok[tok] = 2.f * v + zn;
        if (write_extra) out[OFF_CODE + tok] = (float)id;
        s_code[tid] = id;
        if (v2 - v < TAU) {
            int slot = atomicAdd(&g_nrescue, 1);
            g_rescue[slot] = tok;
        }
    }
    __syncthreads();

#pragma unroll 1
    for (int j = 0; j < 64; j++) {
        int idx = tid + j * 256;
        int row = idx >> 7, q = idx & 127;
        int c = s_code[row];
        float4 vv = *(const float4*)&g_M[(size_t)c * DDIM + q * 4];
        *(float4*)&out[(size_t)(tok0 + row) * DDIM + q * 4] = vv;
    }
}

// ---------------------------------------------------------------------------
// Rescue: bit-exact replica of the R3 kernel's scoring arithmetic.
//   z_e[e]  = in-order k=0..511 fp32 FMA chain of z[k]*wd[e][k]
//   dot_j   = in-order e=0..255 fp32 FMA chain of z_e[e]*cb[j][e]
//   s_j     = fsub(cnh_j, dot_j);  winner = lowest-index min
// Batched 8 tokens per block iteration to amortize wd/cb L2 traffic.
// ---------------------------------------------------------------------------
#define RB 8
__global__ __launch_bounds__(128) void k_rescue(
    const float* __restrict__ z, const float* __restrict__ cb,
    const float* __restrict__ wd, float* __restrict__ out, int write_extra)
{
    __shared__ float zr[RB][512];
    __shared__ float ze[RB][256];
    __shared__ float rbd[RB][128];
    __shared__ int   rbi[RB][128];
    __shared__ float rzn[RB][128];
    __shared__ int   stok[RB];

    int tid = threadIdx.x;
    int n = g_nrescue;
    for (int base = blockIdx.x * RB; base < n; base += gridDim.x * RB) {
        int nt = n - base; if (nt > RB) nt = RB;
        if (tid < nt) stok[tid] = g_rescue[base + tid];
        __syncthreads();
        for (int t = 0; t < nt; t++)
            ((float4*)zr[t])[tid] = ((const float4*)&z[(size_t)stok[t] * DDIM])[tid];
        __syncthreads();

        // exact z_e: thread -> columns (2*tid, 2*tid+1) for all nt tokens
        {
            int e0 = tid * 2;
            const float* w0 = wd + (size_t)e0 * DDIM;
            const float* w1 = w0 + DDIM;
            float s0[RB], s1[RB];
#pragma unroll
            for (int t = 0; t < RB; t++) { s0[t] = 0.f; s1[t] = 0.f; }
#pragma unroll 4
            for (int kb = 0; kb < 512; kb += 8) {
                float a0[8], a1[8];
#pragma unroll
                for (int q = 0; q < 8; q++) { a0[q] = w0[kb + q]; a1[q] = w1[kb + q]; }
                for (int t = 0; t < nt; t++) {
#pragma unroll
                    for (int q = 0; q < 8; q++) {
                        float zv = zr[t][kb + q];
                        s0[t] = __fmaf_rn(zv, a0[q], s0[t]);
                        s1[t] = __fmaf_rn(zv, a1[q], s1[t]);
                    }
                }
            }
            for (int t = 0; t < nt; t++) { ze[t][e0] = s0[t]; ze[t][e0 + 1] = s1[t]; }
        }
        __syncthreads();

        // exact scores: thread owns codes {c*128+tid}, ascending c
        {
            float best[RB]; int bidx[RB]; float znp[RB];
#pragma unroll
            for (int t = 0; t < RB; t++) { best[t] = 3.4e38f; bidx[t] = 0; }
            for (int t = 0; t < nt; t++) {
                float a = ze[t][2 * tid], b = ze[t][2 * tid + 1];
                znp[t] = a * a + b * b;
            }
#pragma unroll 1
            for (int c = 0; c < 8; c++) {
                int j = c * 128 + tid;
                const float* cr = cb + (size_t)j * EDIM;
                float cn = __ldg(&g_cnh[j]);
                float dot[RB];
#pragma unroll
                for (int t = 0; t < RB; t++) dot[t] = 0.f;
#pragma unroll 4
                for (int kb = 0; kb < 256; kb += 8) {
                    float c8[8];
#pragma unroll
                    for (int q = 0; q < 8; q++) c8[q] = cr[kb + q];
                    for (int t = 0; t < nt; t++) {
#pragma unroll
                        for (int q = 0; q < 8; q++)
                            dot[t] = __fmaf_rn(ze[t][kb + q], c8[q], dot[t]);
                    }
                }
                for (int t = 0; t < nt; t++) {
                    float s = cn - dot[t];
                    if (s < best[t]) { best[t] = s; bidx[t] = j; }
                }
            }
            for (int t = 0; t < nt; t++) {
                rbd[t][tid] = best[t]; rbi[t][tid] = bidx[t]; rzn[t][tid] = znp[t];
            }
        }
        __syncthreads();
        for (int off = 64; off > 0; off >>= 1) {
            if (tid < off) {
                for (int t = 0; t < nt; t++) {
                    float ov = rbd[t][tid + off]; int oi = rbi[t][tid + off];
                    if (ov < rbd[t][tid] || (ov == rbd[t][tid] && oi < rbi[t][tid])) {
                        rbd[t][tid] = ov; rbi[t][tid] = oi;
                    }
                    rzn[t][tid] += rzn[t][tid + off];
                }
            }
            __syncthreads();
        }
        for (int t = 0; t < nt; t++) {
            int tok = stok[t]; int cw = rbi[t][0];
            ((float4*)&out[(size_t)tok * DDIM])[tid] = ((const float4*)&g_M[(size_t)cw * DDIM])[tid];
            if (tid == 0) {
                g_lossTok[tok] = 2.f * rbd[t][0] + rzn[t][0];
                if (write_extra) out[OFF_CODE + tok] = (float)cw;
            }
        }
        __syncthreads();
    }
}

// ---------------------------------------------------------------------------
__global__ void k_finalize(float* __restrict__ out) {
    __shared__ float p[128];
    int b = blockIdx.x, tid = threadIdx.x;
    float s = 0.f;
    for (int q = 0; q < 32; q++) s += g_lossTok[b * TLEN + tid * 32 + q];
    p[tid] = s;
    __syncthreads();
    for (int off = 64; off > 0; off >>= 1) {
        if (tid < off) p[tid] += p[tid + off];
        __syncthreads();
    }
    if (tid == 0) {
        float loss = p[0] * (1.0f / ((float)TLEN * (float)EDIM));
        out[OFF_L1 + b] = loss;
        out[OFF_L2 + b] = loss;
    }
}

// ---------------------------------------------------------------------------
extern "C" void kernel_launch(void* const* d_in, const int* in_sizes, int n_in,
                              void* d_out, int out_size) {
    const float* z  = (const float*)d_in[0];
    const float* cb = (const float*)d_in[1];
    const float* wd = (const float*)d_in[2];
    const float* wu = (const float*)d_in[3];
    float* out = (float*)d_out;

    int write_extra = ((size_t)out_size >= OUT_FULL) ? 1 : 0;

    cudaFuncSetAttribute(vq_mma, cudaFuncAttributeMaxDynamicSharedMemorySize, SM_TOTAL);

    k_prep_split<<<1536, 256>>>(wd, cb);
    k_prep_cnh<<<4, 256>>>(cb);
    k_prep_M<<<2048, 256>>>(cb, wu);
    vq_mma<<<NTILES, 256, SM_TOTAL>>>(z, out, write_extra);
    k_rescue<<<256, 128>>>(z, cb, wd, out, write_extra);
    k_finalize<<<BATCH, 128>>>(out);
}

// round 12
// speedup vs baseline: 1.5655x; 1.1091x over previous
#include <cuda_runtime.h>
#include <cuda_bf16.h>
#include <cstdint>

// ---------------------------------------------------------------------------
// Problem constants
// ---------------------------------------------------------------------------
#define BATCH 16
#define TLEN  4096
#define NTOK  (BATCH * TLEN)   // 65536
#define DDIM  512
#define EDIM  256
#define NCODE 1024

#define N_ZOUT   ((size_t)NTOK * DDIM)
#define OFF_L1   (N_ZOUT)
#define OFF_L2   (N_ZOUT + 16)
#define OFF_CODE (N_ZOUT + 32)
#define OUT_FULL (N_ZOUT + 32 + NTOK)

#define TILE_M 64
#define NTILES (NTOK / TILE_M)   // 1024
#define TAU 0.02f                // rescue threshold on half-score gap

typedef unsigned long long u64;
typedef unsigned int u32;

// ---------------------------------------------------------------------------
// Device scratch
// ---------------------------------------------------------------------------
__device__ __nv_bfloat16 g_wdhi[EDIM * DDIM];   // w_down [e][k] hi
__device__ __nv_bfloat16 g_wdlo[EDIM * DDIM];
__device__ __nv_bfloat16 g_cbhi[NCODE * EDIM];  // codebook [j][e] hi
__device__ __nv_bfloat16 g_cblo[NCODE * EDIM];
__device__ float g_cnh[NCODE];                  // 0.5*||c_j||^2
__device__ float g_M[NCODE * DDIM];             // codebook @ w_up^T
__device__ float g_lossTok[NTOK];
__device__ int   g_rescue[NTOK];
__device__ int   g_nrescue;

// ---------------------------------------------------------------------------
// mma / ldmatrix helpers (base-arch PTX)
// ---------------------------------------------------------------------------
__device__ __forceinline__ u32 smem_u32(const void* p) {
    u32 a;
    asm("{ .reg .u64 t; cvta.to.shared.u64 t, %1; cvt.u32.u64 %0, t; }" : "=r"(a) : "l"(p));
    return a;
}

__device__ __forceinline__ void ldsm4(u32 addr, u32& r0, u32& r1, u32& r2, u32& r3) {
    asm volatile("ldmatrix.sync.aligned.m8n8.x4.shared.b16 {%0,%1,%2,%3}, [%4];"
                 : "=r"(r0), "=r"(r1), "=r"(r2), "=r"(r3) : "r"(addr));
}
__device__ __forceinline__ void ldsm2(u32 addr, u32& r0, u32& r1) {
    asm volatile("ldmatrix.sync.aligned.m8n8.x2.shared.b16 {%0,%1}, [%2];"
                 : "=r"(r0), "=r"(r1) : "r"(addr));
}
__device__ __forceinline__ void mma16816(float* c, const u32* a, const u32* b) {
    asm volatile(
        "mma.sync.aligned.m16n8k16.row.col.f32.bf16.bf16.f32 "
        "{%0,%1,%2,%3}, {%4,%5,%6,%7}, {%8,%9}, {%0,%1,%2,%3};"
        : "+f"(c[0]), "+f"(c[1]), "+f"(c[2]), "+f"(c[3])
        : "r"(a[0]), "r"(a[1]), "r"(a[2]), "r"(a[3]), "r"(b[0]), "r"(b[1]));
}

__device__ __forceinline__ u32 pack_hi(float a, float b) {
    __nv_bfloat162 t; t.x = __float2bfloat16(a); t.y = __float2bfloat16(b);
    return *(u32*)&t;
}
__device__ __forceinline__ u32 pack_lo(float a, float b) {
    __nv_bfloat162 t;
    t.x = __float2bfloat16(a - __bfloat162float(__float2bfloat16(a)));
    t.y = __float2bfloat16(b - __bfloat162float(__float2bfloat16(b)));
    return *(u32*)&t;
}

// ---------------------------------------------------------------------------
// Prep kernels (identical numerics to R11)
// ---------------------------------------------------------------------------
__global__ void k_prep_split(const float* __restrict__ wd, const float* __restrict__ cb) {
    int b = blockIdx.x, tid = threadIdx.x;
    if (b < 512) {
        int idx = b * 256 + tid;
        float v = wd[idx];
        __nv_bfloat16 hi = __float2bfloat16(v);
        g_wdhi[idx] = hi;
        g_wdlo[idx] = __float2bfloat16(v - __bfloat162float(hi));
    } else {
        int idx = (b - 512) * 256 + tid;
        float v = cb[idx];
        __nv_bfloat16 hi = __float2bfloat16(v);
        g_cbhi[idx] = hi;
        g_cblo[idx] = __float2bfloat16(v - __bfloat162float(hi));
    }
}

__global__ void k_prep_cnh(const float* __restrict__ cb) {
    int j = blockIdx.x * 256 + threadIdx.x;
    if (j == 0) g_nrescue = 0;
    if (j < NCODE) {
        const float4* r = (const float4*)(cb + (size_t)j * EDIM);
        float s = 0.f;
#pragma unroll 8
        for (int q = 0; q < EDIM / 4; q++) {
            float4 v = r[q];
            s += v.x * v.x + v.y * v.y + v.z * v.z + v.w * v.w;
        }
        g_cnh[j] = 0.5f * s;
    }
}

__global__ void k_prep_M(const float* __restrict__ cb, const float* __restrict__ wu) {
    __shared__ float scb[8 * 256];
    __shared__ float swu[32 * 260];
    int tid = threadIdx.x;
    int j0 = (blockIdx.x >> 4) * 8;
    int d0 = (blockIdx.x & 15) * 32;
#pragma unroll
    for (int r = 0; r < 2; r++) {
        int idx = tid + r * 256;
        int row = idx >> 6, q = (idx & 63) << 2;
        *(float4*)&scb[row * 256 + q] = *(const float4*)&cb[(size_t)(j0 + row) * EDIM + q];
    }
#pragma unroll
    for (int r = 0; r < 8; r++) {
        int idx = tid + r * 256;
        int row = idx >> 6, q = (idx & 63) << 2;
        *(float4*)&swu[row * 260 + q] = *(const float4*)&wu[(size_t)(d0 + row) * EDIM + q];
    }
    __syncthreads();
    int jl = tid >> 5, dl = tid & 31;
    float s = 0.f;
#pragma unroll 16
    for (int e = 0; e < 256; e += 4) {
        float4 a = *(float4*)&scb[jl * 256 + e];
        float4 b = *(float4*)&swu[dl * 260 + e];
        s += a.x * b.x + a.y * b.y + a.z * b.z + a.w * b.w;
    }
    g_M[(size_t)(j0 + jl) * DDIM + d0 + dl] = s;
}

// ---------------------------------------------------------------------------
// Main kernel: 64 tokens/CTA, 8 warps, 2 CTAs/SM. bf16 hi/lo 3-term mma.sync.
// Smem (dynamic, bytes):
//   ZEHI @0      [64][264] bf16 (33792)
//   ZELO @33792  [64][264] bf16 (33792)      end 67584
//   phase1 overlay @67584: AZHI[64][24], AZLO, BWHI[256][24], BWLO (30720)
//   phase2 overlay @67584: BHI[128][72], BLO (36864)   end 104448
// ---------------------------------------------------------------------------
#define OFF_ZEHI 0
#define OFF_ZELO 33792
#define OFF_P    67584
#define OFF_AZHI (OFF_P)
#define OFF_AZLO (OFF_P + 3072)
#define OFF_BWHI (OFF_P + 6144)
#define OFF_BWLO (OFF_P + 18432)
#define OFF_BHI  (OFF_P)
#define OFF_BLO  (OFF_P + 18432)
#define SM_TOTAL 104448

__global__ __launch_bounds__(256, 2) void vq_mma(
    const float* __restrict__ z, float* __restrict__ out, int write_extra)
{
    extern __shared__ char sm[];
    __shared__ float s_min[8][64];
    __shared__ float s_min2[8][64];
    __shared__ int   s_idx[8][64];
    __shared__ float s_zn[8][64];
    __shared__ int   s_code[64];

    const int tid = threadIdx.x;
    const int w = tid >> 5, lane = tid & 31;
    const int tok0 = blockIdx.x * TILE_M;
    const u32 smb = smem_u32(sm);

    float acc[4][4][4];
#pragma unroll
    for (int m = 0; m < 4; m++)
#pragma unroll
        for (int nt = 0; nt < 4; nt++)
#pragma unroll
            for (int c = 0; c < 4; c++) acc[m][nt][c] = 0.f;

    // ================= Phase 1: z_e = z @ w_down^T ===========================
    // warp w -> e-columns w*32..+31, 64 tokens, k chunks of 16.
#pragma unroll 1
    for (int kc = 0; kc < 32; kc++) {
        {   // stage z chunk [64 tok][24-stride] hi/lo
            int row = tid >> 2, c4 = tid & 3;
            float4 v = *(const float4*)&z[(size_t)(tok0 + row) * DDIM + kc * 16 + c4 * 4];
            u32 off = (u32)(row * 24 + c4 * 4) * 2;
            *(uint2*)(sm + OFF_AZHI + off) = make_uint2(pack_hi(v.x, v.y), pack_hi(v.z, v.w));
            *(uint2*)(sm + OFF_AZLO + off) = make_uint2(pack_lo(v.x, v.y), pack_lo(v.z, v.w));
        }
#pragma unroll
        for (int j = 0; j < 2; j++) {   // stage w_down [256 e][24-stride]
            int idx = tid + j * 256;    // 512 = 256 rows x 2 halves
            int row = idx >> 1, q = idx & 1;
            u32 doff = (u32)(row * 24 + q * 8) * 2;
            *(uint4*)(sm + OFF_BWHI + doff) = *(const uint4*)&g_wdhi[row * DDIM + kc * 16 + q * 8];
            *(uint4*)(sm + OFF_BWLO + doff) = *(const uint4*)&g_wdlo[row * DDIM + kc * 16 + q * 8];
        }
        __syncthreads();
        {
            u32 bh[4][2], bl[4][2];
#pragma unroll
            for (int nt = 0; nt < 4; nt++) {
                u32 a = (u32)((w * 32 + nt * 8 + (lane & 7)) * 24 + ((lane >> 3) & 1) * 8) * 2;
                ldsm2(smb + OFF_BWHI + a, bh[nt][0], bh[nt][1]);
                ldsm2(smb + OFF_BWLO + a, bl[nt][0], bl[nt][1]);
            }
#pragma unroll
            for (int m = 0; m < 4; m++) {
                u32 ah[4], al[4];
                u32 aA = (u32)((m * 16 + (lane & 15)) * 24 + (lane >> 4) * 8) * 2;
                ldsm4(smb + OFF_AZHI + aA, ah[0], ah[1], ah[2], ah[3]);
                ldsm4(smb + OFF_AZLO + aA, al[0], al[1], al[2], al[3]);
#pragma unroll
                for (int nt = 0; nt < 4; nt++) {
                    mma16816(acc[m][nt], ah, bh[nt]);
                    mma16816(acc[m][nt], al, bh[nt]);
                    mma16816(acc[m][nt], ah, bl[nt]);
                }
            }
        }
        __syncthreads();
    }

    // ---- phase-1 epilogue: exact ||z_e||^2 partials + z_e hi/lo store ----
    {
        float znp[8];
#pragma unroll
        for (int s = 0; s < 8; s++) znp[s] = 0.f;
#pragma unroll
        for (int m = 0; m < 4; m++) {
#pragma unroll
            for (int nt = 0; nt < 4; nt++) {
                float c0 = acc[m][nt][0], c1 = acc[m][nt][1];
                float c2 = acc[m][nt][2], c3 = acc[m][nt][3];
                znp[m * 2]     += c0 * c0 + c1 * c1;
                znp[m * 2 + 1] += c2 * c2 + c3 * c3;
                int e0 = w * 32 + nt * 8 + 2 * (lane & 3);
                int r1 = m * 16 + (lane >> 2);
                u32 o1 = (u32)(r1 * 264 + e0) * 2;
                u32 o2 = (u32)((r1 + 8) * 264 + e0) * 2;
                *(u32*)(sm + OFF_ZEHI + o1) = pack_hi(c0, c1);
                *(u32*)(sm + OFF_ZELO + o1) = pack_lo(c0, c1);
                *(u32*)(sm + OFF_ZEHI + o2) = pack_hi(c2, c3);
                *(u32*)(sm + OFF_ZELO + o2) = pack_lo(c2, c3);
            }
        }
#pragma unroll
        for (int s = 0; s < 8; s++) {
            znp[s] += __shfl_xor_sync(0xffffffffu, znp[s], 1);
            znp[s] += __shfl_xor_sync(0xffffffffu, znp[s], 2);
        }
        if ((lane & 3) == 0) {
#pragma unroll
            for (int m = 0; m < 4; m++) {
                int r1 = m * 16 + (lane >> 2);
                s_zn[w][r1]     = znp[m * 2];
                s_zn[w][r1 + 8] = znp[m * 2 + 1];
            }
        }
    }
    __syncthreads();

    // ================= Phase 2: scores vs 1024 codes (8 chunks of 128) =======
    float minv[8], minv2[8]; int mini[8];
#pragma unroll
    for (int s = 0; s < 8; s++) { minv[s] = 3.4e38f; minv2[s] = 3.4e38f; mini[s] = 0; }

#pragma unroll 1
    for (int jc = 0; jc < 8; jc++) {
        float acc2[4][2][4];
#pragma unroll
        for (int m = 0; m < 4; m++)
#pragma unroll
            for (int nt = 0; nt < 2; nt++)
#pragma unroll
                for (int c = 0; c < 4; c++) acc2[m][nt][c] = 0.f;

#pragma unroll 1
        for (int kc = 0; kc < 4; kc++) {
#pragma unroll
            for (int j = 0; j < 4; j++) {     // B tile [128 codes][72-stride]
                int idx = tid + j * 256;      // 1024 = 128 rows x 8 uint4
                int row = idx >> 3, q = idx & 7;
                u32 doff = (u32)(row * 72 + q * 8) * 2;
                *(uint4*)(sm + OFF_BHI + doff) =
                    *(const uint4*)&g_cbhi[(size_t)(jc * 128 + row) * EDIM + kc * 64 + q * 8];
                *(uint4*)(sm + OFF_BLO + doff) =
                    *(const uint4*)&g_cblo[(size_t)(jc * 128 + row) * EDIM + kc * 64 + q * 8];
            }
            __syncthreads();
#pragma unroll
            for (int ks = 0; ks < 4; ks++) {
                u32 bh[2][2], bl[2][2];
#pragma unroll
                for (int nt = 0; nt < 2; nt++) {
                    u32 a = (u32)((w * 16 + nt * 8 + (lane & 7)) * 72 + ks * 16 + ((lane >> 3) & 1) * 8) * 2;
                    ldsm2(smb + OFF_BHI + a, bh[nt][0], bh[nt][1]);
                    ldsm2(smb + OFF_BLO + a, bl[nt][0], bl[nt][1]);
                }
#pragma unroll
                for (int m = 0; m < 4; m++) {
                    u32 ah[4], al[4];
                    u32 aA = (u32)((m * 16 + (lane & 15)) * 264 + kc * 64 + ks * 16 + (lane >> 4) * 8) * 2;
                    ldsm4(smb + OFF_ZEHI + aA, ah[0], ah[1], ah[2], ah[3]);
                    ldsm4(smb + OFF_ZELO + aA, al[0], al[1], al[2], al[3]);
#pragma unroll
                    for (int nt = 0; nt < 2; nt++) {
                        mma16816(acc2[m][nt], ah, bh[nt]);
                        mma16816(acc2[m][nt], al, bh[nt]);
                        mma16816(acc2[m][nt], ah, bl[nt]);
                    }
                }
            }
            __syncthreads();
        }
        float cn[4];
#pragma unroll
        for (int nt = 0; nt < 2; nt++) {
            int jb = jc * 128 + w * 16 + nt * 8 + 2 * (lane & 3);
            cn[nt * 2]     = __ldg(&g_cnh[jb]);
            cn[nt * 2 + 1] = __ldg(&g_cnh[jb + 1]);
        }
#pragma unroll
        for (int m = 0; m < 4; m++) {
#pragma unroll
            for (int nt = 0; nt < 2; nt++) {
#pragma unroll
                for (int c = 0; c < 4; c++) {
                    float s = cn[nt * 2 + (c & 1)] - acc2[m][nt][c];
                    int code = jc * 128 + w * 16 + nt * 8 + 2 * (lane & 3) + (c & 1);
                    int slot = m * 2 + (c >> 1);
                    if (s < minv[slot]) { minv2[slot] = minv[slot]; minv[slot] = s; mini[slot] = code; }
                    else if (s < minv2[slot]) { minv2[slot] = s; }
                }
            }
        }
    }

#pragma unroll
    for (int s = 0; s < 8; s++) {
#pragma unroll
        for (int off = 1; off <= 2; off <<= 1) {
            float ov  = __shfl_xor_sync(0xffffffffu, minv[s], off);
            float ov2 = __shfl_xor_sync(0xffffffffu, minv2[s], off);
            int   oi  = __shfl_xor_sync(0xffffffffu, mini[s], off);
            float nv2 = fminf(fmaxf(minv[s], ov), fminf(minv2[s], ov2));
            if (ov < minv[s] || (ov == minv[s] && oi < mini[s])) { minv[s] = ov; mini[s] = oi; }
            minv2[s] = nv2;
        }
    }
    if ((lane & 3) == 0) {
#pragma unroll
        for (int m = 0; m < 4; m++) {
            int r1 = m * 16 + (lane >> 2);
            s_min[w][r1] = minv[m * 2];      s_min2[w][r1] = minv2[m * 2];      s_idx[w][r1] = mini[m * 2];
            s_min[w][r1 + 8] = minv[m * 2 + 1]; s_min2[w][r1 + 8] = minv2[m * 2 + 1]; s_idx[w][r1 + 8] = mini[m * 2 + 1];
        }
    }
    __syncthreads();

    if (tid < 64) {
        float v = s_min[0][tid], v2 = s_min2[0][tid], zn = s_zn[0][tid];
        int id = s_idx[0][tid];
#pragma unroll
        for (int ww = 1; ww < 8; ww++) {
            float ov = s_min[ww][tid], ov2 = s_min2[ww][tid];
            int oi = s_idx[ww][tid];
            float nv2 = fminf(fmaxf(v, ov), fminf(v2, ov2));
            if (ov < v || (ov == v && oi < id)) { v = ov; id = oi; }
            v2 = nv2;
            zn += s_zn[ww][tid];
        }
        int tok = tok0 + tid;
        g_lossTok[tok] = 2.f * v + zn;
        if (write_extra) out[OFF_CODE + tok] = (float)id;
        s_code[tid] = id;
        if (v2 - v < TAU) {
            int slot = atomicAdd(&g_nrescue, 1);
            g_rescue[slot] = tok;
        }
    }
    __syncthreads();

#pragma unroll 1
    for (int j = 0; j < 32; j++) {       // z_out gather from M
        int idx = tid + j * 256;         // 8192 float4
        int row = idx >> 7, q = idx & 127;
        int c = s_code[row];
        float4 vv = *(const float4*)&g_M[(size_t)c * DDIM + q * 4];
        *(float4*)&out[(size_t)(tok0 + row) * DDIM + q * 4] = vv;
    }
}

// ---------------------------------------------------------------------------
// Rescue: UNCHANGED arithmetic from R11 (bit-exact R3 replica). Wider grid.
// ---------------------------------------------------------------------------
#define RB 8
__global__ __launch_bounds__(128) void k_rescue(
    const float* __restrict__ z, const float* __restrict__ cb,
    const float* __restrict__ wd, float* __restrict__ out, int write_extra)
{
    __shared__ float zr[RB][512];
    __shared__ float ze[RB][256];
    __shared__ float rbd[RB][128];
    __shared__ int   rbi[RB][128];
    __shared__ float rzn[RB][128];
    __shared__ int   stok[RB];

    int tid = threadIdx.x;
    int n = g_nrescue;
    for (int base = blockIdx.x * RB; base < n; base += gridDim.x * RB) {
        int nt = n - base; if (nt > RB) nt = RB;
        if (tid < nt) stok[tid] = g_rescue[base + tid];
        __syncthreads();
        for (int t = 0; t < nt; t++)
            ((float4*)zr[t])[tid] = ((const float4*)&z[(size_t)stok[t] * DDIM])[tid];
        __syncthreads();

        {
            int e0 = tid * 2;
            const float* w0 = wd + (size_t)e0 * DDIM;
            const float* w1 = w0 + DDIM;
            float s0[RB], s1[RB];
#pragma unroll
            for (int t = 0; t < RB; t++) { s0[t] = 0.f; s1[t] = 0.f; }
#pragma unroll 4
            for (int kb = 0; kb < 512; kb += 8) {
                float a0[8], a1[8];
#pragma unroll
                for (int q = 0; q < 8; q++) { a0[q] = w0[kb + q]; a1[q] = w1[kb + q]; }
                for (int t = 0; t < nt; t++) {
#pragma unroll
                    for (int q = 0; q < 8; q++) {
                        float zv = zr[t][kb + q];
                        s0[t] = __fmaf_rn(zv, a0[q], s0[t]);
                        s1[t] = __fmaf_rn(zv, a1[q], s1[t]);
                    }
                }
            }
            for (int t = 0; t < nt; t++) { ze[t][e0] = s0[t]; ze[t][e0 + 1] = s1[t]; }
        }
        __syncthreads();

        {
            float best[RB]; int bidx[RB]; float znp[RB];
#pragma unroll
            for (int t = 0; t < RB; t++) { best[t] = 3.4e38f; bidx[t] = 0; }
            for (int t = 0; t < nt; t++) {
                float a = ze[t][2 * tid], b = ze[t][2 * tid + 1];
                znp[t] = a * a + b * b;
            }
#pragma unroll 1
            for (int c = 0; c < 8; c++) {
                int j = c * 128 + tid;
                const float* cr = cb + (size_t)j * EDIM;
                float cn = __ldg(&g_cnh[j]);
                float dot[RB];
#pragma unroll
                for (int t = 0; t < RB; t++) dot[t] = 0.f;
#pragma unroll 4
                for (int kb = 0; kb < 256; kb += 8) {
                    float c8[8];
#pragma unroll
                    for (int q = 0; q < 8; q++) c8[q] = cr[kb + q];
                    for (int t = 0; t < nt; t++) {
#pragma unroll
                        for (int q = 0; q < 8; q++)
                            dot[t] = __fmaf_rn(ze[t][kb + q], c8[q], dot[t]);
                    }
                }
                for (int t = 0; t < nt; t++) {
                    float s = cn - dot[t];
                    if (s < best[t]) { best[t] = s; bidx[t] = j; }
                }
            }
            for (int t = 0; t < nt; t++) {
                rbd[t][tid] = best[t]; rbi[t][tid] = bidx[t]; rzn[t][tid] = znp[t];
            }
        }
        __syncthreads();
        for (int off = 64; off > 0; off >>= 1) {
            if (tid < off) {
                for (int t = 0; t < nt; t++) {
                    float ov = rbd[t][tid + off]; int oi = rbi[t][tid + off];
                    if (ov < rbd[t][tid] || (ov == rbd[t][tid] && oi < rbi[t][tid])) {
                        rbd[t][tid] = ov; rbi[t][tid] = oi;
                    }
                    rzn[t][tid] += rzn[t][tid + off];
                }
            }
            __syncthreads();
        }
        for (int t = 0; t < nt; t++) {
            int tok = stok[t]; int cw = rbi[t][0];
            ((float4*)&out[(size_t)tok * DDIM])[tid] = ((const float4*)&g_M[(size_t)cw * DDIM])[tid];
            if (tid == 0) {
                g_lossTok[tok] = 2.f * rbd[t][0] + rzn[t][0];
                if (write_extra) out[OFF_CODE + tok] = (float)cw;
            }
        }
        __syncthreads();
    }
}

// ---------------------------------------------------------------------------
__global__ void k_finalize(float* __restrict__ out) {
    __shared__ float p[128];
    int b = blockIdx.x, tid = threadIdx.x;
    float s = 0.f;
    for (int q = 0; q < 32; q++) s += g_lossTok[b * TLEN + tid * 32 + q];
    p[tid] = s;
    __syncthreads();
    for (int off = 64; off > 0; off >>= 1) {
        if (tid < off) p[tid] += p[tid + off];
        __syncthreads();
    }
    if (tid == 0) {
        float loss = p[0] * (1.0f / ((float)TLEN * (float)EDIM));
        out[OFF_L1 + b] = loss;
        out[OFF_L2 + b] = loss;
    }
}

// ---------------------------------------------------------------------------
extern "C" void kernel_launch(void* const* d_in, const int* in_sizes, int n_in,
                              void* d_out, int out_size) {
    const float* z  = (const float*)d_in[0];
    const float* cb = (const float*)d_in[1];
    const float* wd = (const float*)d_in[2];
    const float* wu = (const float*)d_in[3];
    float* out = (float*)d_out;

    int write_extra = ((size_t)out_size >= OUT_FULL) ? 1 : 0;

    cudaFuncSetAttribute(vq_mma, cudaFuncAttributeMaxDynamicSharedMemorySize, SM_TOTAL);

    k_prep_split<<<1536, 256>>>(wd, cb);
    k_prep_cnh<<<4, 256>>>(cb);
    k_prep_M<<<2048, 256>>>(cb, wu);
    vq_mma<<<NTILES, 256, SM_TOTAL>>>(z, out, write_extra);
    k_rescue<<<1024, 128>>>(z, cb, wd, out, write_extra);
    k_finalize<<<BATCH, 128>>>(out);
}

// round 13
// speedup vs baseline: 1.6055x; 1.0256x over previous
#include <cuda_runtime.h>
#include <cuda_bf16.h>
#include <cstdint>

// ---------------------------------------------------------------------------
// Problem constants
// ---------------------------------------------------------------------------
#define BATCH 16
#define TLEN  4096
#define NTOK  (BATCH * TLEN)   // 65536
#define DDIM  512
#define EDIM  256
#define NCODE 1024

#define N_ZOUT   ((size_t)NTOK * DDIM)
#define OFF_L1   (N_ZOUT)
#define OFF_L2   (N_ZOUT + 16)
#define OFF_CODE (N_ZOUT + 32)
#define OUT_FULL (N_ZOUT + 32 + NTOK)

#define TILE_M 64
#define NTILES (NTOK / TILE_M)   // 1024
#define TAU 0.02f                // rescue threshold on half-score gap

typedef unsigned long long u64;
typedef unsigned int u32;

// ---------------------------------------------------------------------------
// Device scratch
// ---------------------------------------------------------------------------
__device__ __nv_bfloat16 g_wdhi[EDIM * DDIM];   // w_down [e][k] hi
__device__ __nv_bfloat16 g_wdlo[EDIM * DDIM];
__device__ __nv_bfloat16 g_cbhi[NCODE * EDIM];  // codebook [j][e] hi
__device__ __nv_bfloat16 g_cblo[NCODE * EDIM];
__device__ float g_cnh[NCODE];                  // 0.5*||c_j||^2
__device__ float g_M[NCODE * DDIM];             // codebook @ w_up^T
__device__ float g_lossTok[NTOK];
__device__ int   g_rescue[NTOK];
__device__ int   g_nrescue;

// ---------------------------------------------------------------------------
// mma / ldmatrix helpers (base-arch PTX)
// ---------------------------------------------------------------------------
__device__ __forceinline__ u32 smem_u32(const void* p) {
    u32 a;
    asm("{ .reg .u64 t; cvta.to.shared.u64 t, %1; cvt.u32.u64 %0, t; }" : "=r"(a) : "l"(p));
    return a;
}

__device__ __forceinline__ void ldsm4(u32 addr, u32& r0, u32& r1, u32& r2, u32& r3) {
    asm volatile("ldmatrix.sync.aligned.m8n8.x4.shared.b16 {%0,%1,%2,%3}, [%4];"
                 : "=r"(r0), "=r"(r1), "=r"(r2), "=r"(r3) : "r"(addr));
}
__device__ __forceinline__ void ldsm2(u32 addr, u32& r0, u32& r1) {
    asm volatile("ldmatrix.sync.aligned.m8n8.x2.shared.b16 {%0,%1}, [%2];"
                 : "=r"(r0), "=r"(r1) : "r"(addr));
}
__device__ __forceinline__ void mma16816(float* c, const u32* a, const u32* b) {
    asm volatile(
        "mma.sync.aligned.m16n8k16.row.col.f32.bf16.bf16.f32 "
        "{%0,%1,%2,%3}, {%4,%5,%6,%7}, {%8,%9}, {%0,%1,%2,%3};"
        : "+f"(c[0]), "+f"(c[1]), "+f"(c[2]), "+f"(c[3])
        : "r"(a[0]), "r"(a[1]), "r"(a[2]), "r"(a[3]), "r"(b[0]), "r"(b[1]));
}

__device__ __forceinline__ u32 pack_hi(float a, float b) {
    __nv_bfloat162 t; t.x = __float2bfloat16(a); t.y = __float2bfloat16(b);
    return *(u32*)&t;
}
__device__ __forceinline__ u32 pack_lo(float a, float b) {
    __nv_bfloat162 t;
    t.x = __float2bfloat16(a - __bfloat162float(__float2bfloat16(a)));
    t.y = __float2bfloat16(b - __bfloat162float(__float2bfloat16(b)));
    return *(u32*)&t;
}

// ---------------------------------------------------------------------------
// Prep kernels (identical numerics; cnh folded into split)
// ---------------------------------------------------------------------------
__global__ void k_prep_split(const float* __restrict__ wd, const float* __restrict__ cb) {
    int b = blockIdx.x, tid = threadIdx.x;
    if (b < 512) {
        int idx = b * 256 + tid;
        float v = wd[idx];
        __nv_bfloat16 hi = __float2bfloat16(v);
        g_wdhi[idx] = hi;
        g_wdlo[idx] = __float2bfloat16(v - __bfloat162float(hi));
    } else if (b < 1536) {
        int idx = (b - 512) * 256 + tid;
        float v = cb[idx];
        __nv_bfloat16 hi = __float2bfloat16(v);
        g_cbhi[idx] = hi;
        g_cblo[idx] = __float2bfloat16(v - __bfloat162float(hi));
    } else {
        int j = (b - 1536) * 256 + tid;
        if (j == 0) g_nrescue = 0;
        if (j < NCODE) {
            const float4* r = (const float4*)(cb + (size_t)j * EDIM);
            float s = 0.f;
#pragma unroll 8
            for (int q = 0; q < EDIM / 4; q++) {
                float4 v = r[q];
                s += v.x * v.x + v.y * v.y + v.z * v.z + v.w * v.w;
            }
            g_cnh[j] = 0.5f * s;
        }
    }
}

__global__ void k_prep_M(const float* __restrict__ cb, const float* __restrict__ wu) {
    __shared__ float scb[8 * 256];
    __shared__ float swu[32 * 260];
    int tid = threadIdx.x;
    int j0 = (blockIdx.x >> 4) * 8;
    int d0 = (blockIdx.x & 15) * 32;
#pragma unroll
    for (int r = 0; r < 2; r++) {
        int idx = tid + r * 256;
        int row = idx >> 6, q = (idx & 63) << 2;
        *(float4*)&scb[row * 256 + q] = *(const float4*)&cb[(size_t)(j0 + row) * EDIM + q];
    }
#pragma unroll
    for (int r = 0; r < 8; r++) {
        int idx = tid + r * 256;
        int row = idx >> 6, q = (idx & 63) << 2;
        *(float4*)&swu[row * 260 + q] = *(const float4*)&wu[(size_t)(d0 + row) * EDIM + q];
    }
    __syncthreads();
    int jl = tid >> 5, dl = tid & 31;
    float s = 0.f;
#pragma unroll 16
    for (int e = 0; e < 256; e += 4) {
        float4 a = *(float4*)&scb[jl * 256 + e];
        float4 b = *(float4*)&swu[dl * 260 + e];
        s += a.x * b.x + a.y * b.y + a.z * b.z + a.w * b.w;
    }
    g_M[(size_t)(j0 + jl) * DDIM + d0 + dl] = s;
}

// ---------------------------------------------------------------------------
// Main kernel: UNCHANGED from R12 (known-good 586us).
// ---------------------------------------------------------------------------
#define OFF_ZEHI 0
#define OFF_ZELO 33792
#define OFF_P    67584
#define OFF_AZHI (OFF_P)
#define OFF_AZLO (OFF_P + 3072)
#define OFF_BWHI (OFF_P + 6144)
#define OFF_BWLO (OFF_P + 18432)
#define OFF_BHI  (OFF_P)
#define OFF_BLO  (OFF_P + 18432)
#define SM_TOTAL 104448

__global__ __launch_bounds__(256, 2) void vq_mma(
    const float* __restrict__ z, float* __restrict__ out, int write_extra)
{
    extern __shared__ char sm[];
    __shared__ float s_min[8][64];
    __shared__ float s_min2[8][64];
    __shared__ int   s_idx[8][64];
    __shared__ float s_zn[8][64];
    __shared__ int   s_code[64];

    const int tid = threadIdx.x;
    const int w = tid >> 5, lane = tid & 31;
    const int tok0 = blockIdx.x * TILE_M;
    const u32 smb = smem_u32(sm);

    float acc[4][4][4];
#pragma unroll
    for (int m = 0; m < 4; m++)
#pragma unroll
        for (int nt = 0; nt < 4; nt++)
#pragma unroll
            for (int c = 0; c < 4; c++) acc[m][nt][c] = 0.f;

    // ================= Phase 1: z_e = z @ w_down^T ===========================
#pragma unroll 1
    for (int kc = 0; kc < 32; kc++) {
        {
            int row = tid >> 2, c4 = tid & 3;
            float4 v = *(const float4*)&z[(size_t)(tok0 + row) * DDIM + kc * 16 + c4 * 4];
            u32 off = (u32)(row * 24 + c4 * 4) * 2;
            *(uint2*)(sm + OFF_AZHI + off) = make_uint2(pack_hi(v.x, v.y), pack_hi(v.z, v.w));
            *(uint2*)(sm + OFF_AZLO + off) = make_uint2(pack_lo(v.x, v.y), pack_lo(v.z, v.w));
        }
#pragma unroll
        for (int j = 0; j < 2; j++) {
            int idx = tid + j * 256;
            int row = idx >> 1, q = idx & 1;
            u32 doff = (u32)(row * 24 + q * 8) * 2;
            *(uint4*)(sm + OFF_BWHI + doff) = *(const uint4*)&g_wdhi[row * DDIM + kc * 16 + q * 8];
            *(uint4*)(sm + OFF_BWLO + doff) = *(const uint4*)&g_wdlo[row * DDIM + kc * 16 + q * 8];
        }
        __syncthreads();
        {
            u32 bh[4][2], bl[4][2];
#pragma unroll
            for (int nt = 0; nt < 4; nt++) {
                u32 a = (u32)((w * 32 + nt * 8 + (lane & 7)) * 24 + ((lane >> 3) & 1) * 8) * 2;
                ldsm2(smb + OFF_BWHI + a, bh[nt][0], bh[nt][1]);
                ldsm2(smb + OFF_BWLO + a, bl[nt][0], bl[nt][1]);
            }
#pragma unroll
            for (int m = 0; m < 4; m++) {
                u32 ah[4], al[4];
                u32 aA = (u32)((m * 16 + (lane & 15)) * 24 + (lane >> 4) * 8) * 2;
                ldsm4(smb + OFF_AZHI + aA, ah[0], ah[1], ah[2], ah[3]);
                ldsm4(smb + OFF_AZLO + aA, al[0], al[1], al[2], al[3]);
#pragma unroll
                for (int nt = 0; nt < 4; nt++) {
                    mma16816(acc[m][nt], ah, bh[nt]);
                    mma16816(acc[m][nt], al, bh[nt]);
                    mma16816(acc[m][nt], ah, bl[nt]);
                }
            }
        }
        __syncthreads();
    }

    // ---- phase-1 epilogue ----
    {
        float znp[8];
#pragma unroll
        for (int s = 0; s < 8; s++) znp[s] = 0.f;
#pragma unroll
        for (int m = 0; m < 4; m++) {
#pragma unroll
            for (int nt = 0; nt < 4; nt++) {
                float c0 = acc[m][nt][0], c1 = acc[m][nt][1];
                float c2 = acc[m][nt][2], c3 = acc[m][nt][3];
                znp[m * 2]     += c0 * c0 + c1 * c1;
                znp[m * 2 + 1] += c2 * c2 + c3 * c3;
                int e0 = w * 32 + nt * 8 + 2 * (lane & 3);
                int r1 = m * 16 + (lane >> 2);
                u32 o1 = (u32)(r1 * 264 + e0) * 2;
                u32 o2 = (u32)((r1 + 8) * 264 + e0) * 2;
                *(u32*)(sm + OFF_ZEHI + o1) = pack_hi(c0, c1);
                *(u32*)(sm + OFF_ZELO + o1) = pack_lo(c0, c1);
                *(u32*)(sm + OFF_ZEHI + o2) = pack_hi(c2, c3);
                *(u32*)(sm + OFF_ZELO + o2) = pack_lo(c2, c3);
            }
        }
#pragma unroll
        for (int s = 0; s < 8; s++) {
            znp[s] += __shfl_xor_sync(0xffffffffu, znp[s], 1);
            znp[s] += __shfl_xor_sync(0xffffffffu, znp[s], 2);
        }
        if ((lane & 3) == 0) {
#pragma unroll
            for (int m = 0; m < 4; m++) {
                int r1 = m * 16 + (lane >> 2);
                s_zn[w][r1]     = znp[m * 2];
                s_zn[w][r1 + 8] = znp[m * 2 + 1];
            }
        }
    }
    __syncthreads();

    // ================= Phase 2: scores vs 1024 codes =========================
    float minv[8], minv2[8]; int mini[8];
#pragma unroll
    for (int s = 0; s < 8; s++) { minv[s] = 3.4e38f; minv2[s] = 3.4e38f; mini[s] = 0; }

#pragma unroll 1
    for (int jc = 0; jc < 8; jc++) {
        float acc2[4][2][4];
#pragma unroll
        for (int m = 0; m < 4; m++)
#pragma unroll
            for (int nt = 0; nt < 2; nt++)
#pragma unroll
                for (int c = 0; c < 4; c++) acc2[m][nt][c] = 0.f;

#pragma unroll 1
        for (int kc = 0; kc < 4; kc++) {
#pragma unroll
            for (int j = 0; j < 4; j++) {
                int idx = tid + j * 256;
                int row = idx >> 3, q = idx & 7;
                u32 doff = (u32)(row * 72 + q * 8) * 2;
                *(uint4*)(sm + OFF_BHI + doff) =
                    *(const uint4*)&g_cbhi[(size_t)(jc * 128 + row) * EDIM + kc * 64 + q * 8];
                *(uint4*)(sm + OFF_BLO + doff) =
                    *(const uint4*)&g_cblo[(size_t)(jc * 128 + row) * EDIM + kc * 64 + q * 8];
            }
            __syncthreads();
#pragma unroll
            for (int ks = 0; ks < 4; ks++) {
                u32 bh[2][2], bl[2][2];
#pragma unroll
                for (int nt = 0; nt < 2; nt++) {
                    u32 a = (u32)((w * 16 + nt * 8 + (lane & 7)) * 72 + ks * 16 + ((lane >> 3) & 1) * 8) * 2;
                    ldsm2(smb + OFF_BHI + a, bh[nt][0], bh[nt][1]);
                    ldsm2(smb + OFF_BLO + a, bl[nt][0], bl[nt][1]);
                }
#pragma unroll
                for (int m = 0; m < 4; m++) {
                    u32 ah[4], al[4];
                    u32 aA = (u32)((m * 16 + (lane & 15)) * 264 + kc * 64 + ks * 16 + (lane >> 4) * 8) * 2;
                    ldsm4(smb + OFF_ZEHI + aA, ah[0], ah[1], ah[2], ah[3]);
                    ldsm4(smb + OFF_ZELO + aA, al[0], al[1], al[2], al[3]);
#pragma unroll
                    for (int nt = 0; nt < 2; nt++) {
                        mma16816(acc2[m][nt], ah, bh[nt]);
                        mma16816(acc2[m][nt], al, bh[nt]);
                        mma16816(acc2[m][nt], ah, bl[nt]);
                    }
                }
            }
            __syncthreads();
        }
        float cn[4];
#pragma unroll
        for (int nt = 0; nt < 2; nt++) {
            int jb = jc * 128 + w * 16 + nt * 8 + 2 * (lane & 3);
            cn[nt * 2]     = __ldg(&g_cnh[jb]);
            cn[nt * 2 + 1] = __ldg(&g_cnh[jb + 1]);
        }
#pragma unroll
        for (int m = 0; m < 4; m++) {
#pragma unroll
            for (int nt = 0; nt < 2; nt++) {
#pragma unroll
                for (int c = 0; c < 4; c++) {
                    float s = cn[nt * 2 + (c & 1)] - acc2[m][nt][c];
                    int code = jc * 128 + w * 16 + nt * 8 + 2 * (lane & 3) + (c & 1);
                    int slot = m * 2 + (c >> 1);
                    if (s < minv[slot]) { minv2[slot] = minv[slot]; minv[slot] = s; mini[slot] = code; }
                    else if (s < minv2[slot]) { minv2[slot] = s; }
                }
            }
        }
    }

#pragma unroll
    for (int s = 0; s < 8; s++) {
#pragma unroll
        for (int off = 1; off <= 2; off <<= 1) {
            float ov  = __shfl_xor_sync(0xffffffffu, minv[s], off);
            float ov2 = __shfl_xor_sync(0xffffffffu, minv2[s], off);
            int   oi  = __shfl_xor_sync(0xffffffffu, mini[s], off);
            float nv2 = fminf(fmaxf(minv[s], ov), fminf(minv2[s], ov2));
            if (ov < minv[s] || (ov == minv[s] && oi < mini[s])) { minv[s] = ov; mini[s] = oi; }
            minv2[s] = nv2;
        }
    }
    if ((lane & 3) == 0) {
#pragma unroll
        for (int m = 0; m < 4; m++) {
            int r1 = m * 16 + (lane >> 2);
            s_min[w][r1] = minv[m * 2];      s_min2[w][r1] = minv2[m * 2];      s_idx[w][r1] = mini[m * 2];
            s_min[w][r1 + 8] = minv[m * 2 + 1]; s_min2[w][r1 + 8] = minv2[m * 2 + 1]; s_idx[w][r1 + 8] = mini[m * 2 + 1];
        }
    }
    __syncthreads();

    if (tid < 64) {
        float v = s_min[0][tid], v2 = s_min2[0][tid], zn = s_zn[0][tid];
        int id = s_idx[0][tid];
#pragma unroll
        for (int ww = 1; ww < 8; ww++) {
            float ov = s_min[ww][tid], ov2 = s_min2[ww][tid];
            int oi = s_idx[ww][tid];
            float nv2 = fminf(fmaxf(v, ov), fminf(v2, ov2));
            if (ov < v || (ov == v && oi < id)) { v = ov; id = oi; }
            v2 = nv2;
            zn += s_zn[ww][tid];
        }
        int tok = tok0 + tid;
        g_lossTok[tok] = 2.f * v + zn;
        if (write_extra) out[OFF_CODE + tok] = (float)id;
        s_code[tid] = id;
        if (v2 - v < TAU) {
            int slot = atomicAdd(&g_nrescue, 1);
            g_rescue[slot] = tok;
        }
    }
    __syncthreads();

#pragma unroll 1
    for (int j = 0; j < 32; j++) {
        int idx = tid + j * 256;
        int row = idx >> 7, q = idx & 127;
        int c = s_code[row];
        float4 vv = *(const float4*)&g_M[(size_t)c * DDIM + q * 4];
        *(float4*)&out[(size_t)(tok0 + row) * DDIM + q * 4] = vv;
    }
}

// ---------------------------------------------------------------------------
// Rescue: arithmetic UNCHANGED (bit-exact R3 replica). All loops now
// compile-time RB=8 via token-list padding (duplicate last token) so every
// per-token array stays in registers (no dynamic indexing -> no local mem).
// Duplicated tokens recompute and rewrite identical values (deterministic).
// ---------------------------------------------------------------------------
#define RB 8
__global__ __launch_bounds__(128) void k_rescue(
    const float* __restrict__ z, const float* __restrict__ cb,
    const float* __restrict__ wd, float* __restrict__ out, int write_extra)
{
    __shared__ float zr[RB][512];
    __shared__ float ze[RB][256];
    __shared__ float rbd[RB][128];
    __shared__ int   rbi[RB][128];
    __shared__ float rzn[RB][128];
    __shared__ int   stok[RB];

    int tid = threadIdx.x;
    int n = g_nrescue;
    if (n <= 0) return;
    for (int base = blockIdx.x * RB; base < n; base += gridDim.x * RB) {
        if (tid < RB) {
            int idx = base + tid; if (idx > n - 1) idx = n - 1;
            stok[tid] = g_rescue[idx];
        }
        __syncthreads();
#pragma unroll
        for (int t = 0; t < RB; t++)
            ((float4*)zr[t])[tid] = ((const float4*)&z[(size_t)stok[t] * DDIM])[tid];
        __syncthreads();

        // exact z_e: thread -> columns (2*tid, 2*tid+1), in-order k chain
        {
            int e0 = tid * 2;
            const float* w0 = wd + (size_t)e0 * DDIM;
            const float* w1 = w0 + DDIM;
            float s0[RB], s1[RB];
#pragma unroll
            for (int t = 0; t < RB; t++) { s0[t] = 0.f; s1[t] = 0.f; }
#pragma unroll 4
            for (int kb = 0; kb < 512; kb += 8) {
                float a0[8], a1[8];
#pragma unroll
                for (int q = 0; q < 8; q++) { a0[q] = w0[kb + q]; a1[q] = w1[kb + q]; }
#pragma unroll
                for (int t = 0; t < RB; t++) {
#pragma unroll
                    for (int q = 0; q < 8; q++) {
                        float zv = zr[t][kb + q];
                        s0[t] = __fmaf_rn(zv, a0[q], s0[t]);
                        s1[t] = __fmaf_rn(zv, a1[q], s1[t]);
                    }
                }
            }
#pragma unroll
            for (int t = 0; t < RB; t++) { ze[t][e0] = s0[t]; ze[t][e0 + 1] = s1[t]; }
        }
        __syncthreads();

        // exact scores: thread owns codes {c*128+tid}, ascending c
        {
            float best[RB]; int bidx[RB]; float znp[RB];
#pragma unroll
            for (int t = 0; t < RB; t++) { best[t] = 3.4e38f; bidx[t] = 0; }
#pragma unroll
            for (int t = 0; t < RB; t++) {
                float a = ze[t][2 * tid], b = ze[t][2 * tid + 1];
                znp[t] = a * a + b * b;
            }
#pragma unroll 1
            for (int c = 0; c < 8; c++) {
                int j = c * 128 + tid;
                const float* cr = cb + (size_t)j * EDIM;
                float cn = __ldg(&g_cnh[j]);
                float dot[RB];
#pragma unroll
                for (int t = 0; t < RB; t++) dot[t] = 0.f;
#pragma unroll 4
                for (int kb = 0; kb < 256; kb += 8) {
                    float c8[8];
#pragma unroll
                    for (int q = 0; q < 8; q++) c8[q] = cr[kb + q];
#pragma unroll
                    for (int t = 0; t < RB; t++) {
#pragma unroll
                        for (int q = 0; q < 8; q++)
                            dot[t] = __fmaf_rn(ze[t][kb + q], c8[q], dot[t]);
                    }
                }
#pragma unroll
                for (int t = 0; t < RB; t++) {
                    float s = cn - dot[t];
                    if (s < best[t]) { best[t] = s; bidx[t] = j; }
                }
            }
#pragma unroll
            for (int t = 0; t < RB; t++) {
                rbd[t][tid] = best[t]; rbi[t][tid] = bidx[t]; rzn[t][tid] = znp[t];
            }
        }
        __syncthreads();
        for (int off = 64; off > 0; off >>= 1) {
            if (tid < off) {
#pragma unroll
                for (int t = 0; t < RB; t++) {
                    float ov = rbd[t][tid + off]; int oi = rbi[t][tid + off];
                    if (ov < rbd[t][tid] || (ov == rbd[t][tid] && oi < rbi[t][tid])) {
                        rbd[t][tid] = ov; rbi[t][tid] = oi;
                    }
                    rzn[t][tid] += rzn[t][tid + off];
                }
            }
            __syncthreads();
        }
#pragma unroll
        for (int t = 0; t < RB; t++) {
            int tok = stok[t]; int cw = rbi[t][0];
            ((float4*)&out[(size_t)tok * DDIM])[tid] = ((const float4*)&g_M[(size_t)cw * DDIM])[tid];
            if (tid == 0) {
                g_lossTok[tok] = 2.f * rbd[t][0] + rzn[t][0];
                if (write_extra) out[OFF_CODE + tok] = (float)cw;
            }
        }
        __syncthreads();
    }
}

// ---------------------------------------------------------------------------
__global__ void k_finalize(float* __restrict__ out) {
    __shared__ float p[128];
    int b = blockIdx.x, tid = threadIdx.x;
    float s = 0.f;
    for (int q = 0; q < 32; q++) s += g_lossTok[b * TLEN + tid * 32 + q];
    p[tid] = s;
    __syncthreads();
    for (int off = 64; off > 0; off >>= 1) {
        if (tid < off) p[tid] += p[tid + off];
        __syncthreads();
    }
    if (tid == 0) {
        float loss = p[0] * (1.0f / ((float)TLEN * (float)EDIM));
        out[OFF_L1 + b] = loss;
        out[OFF_L2 + b] = loss;
    }
}

// ---------------------------------------------------------------------------
extern "C" void kernel_launch(void* const* d_in, const int* in_sizes, int n_in,
                              void* d_out, int out_size) {
    const float* z  = (const float*)d_in[0];
    const float* cb = (const float*)d_in[1];
    const float* wd = (const float*)d_in[2];
    const float* wu = (const float*)d_in[3];
    float* out = (float*)d_out;

    int write_extra = ((size_t)out_size >= OUT_FULL) ? 1 : 0;

    cudaFuncSetAttribute(vq_mma, cudaFuncAttributeMaxDynamicSharedMemorySize, SM_TOTAL);

    k_prep_split<<<1540, 256>>>(wd, cb);
    k_prep_M<<<2048, 256>>>(cb, wu);
    vq_mma<<<NTILES, 256, SM_TOTAL>>>(z, out, write_extra);
    k_rescue<<<512, 128>>>(z, cb, wd, out, write_extra);
    k_finalize<<<BATCH, 128>>>(out);
}

// round 14
// speedup vs baseline: 1.6623x; 1.0354x over previous
#include <cuda_runtime.h>
#include <cuda_bf16.h>
#include <cstdint>

// ---------------------------------------------------------------------------
// Problem constants
// ---------------------------------------------------------------------------
#define BATCH 16
#define TLEN  4096
#define NTOK  (BATCH * TLEN)   // 65536
#define DDIM  512
#define EDIM  256
#define NCODE 1024

#define N_ZOUT   ((size_t)NTOK * DDIM)
#define OFF_L1   (N_ZOUT)
#define OFF_L2   (N_ZOUT + 16)
#define OFF_CODE (N_ZOUT + 32)
#define OUT_FULL (N_ZOUT + 32 + NTOK)

#define TILE_M 64
#define NTILES (NTOK / TILE_M)   // 1024
#define TAU 0.02f                // rescue threshold on half-score gap

typedef unsigned long long u64;
typedef unsigned int u32;

// ---------------------------------------------------------------------------
// Device scratch
// ---------------------------------------------------------------------------
__device__ __nv_bfloat16 g_wdhi[EDIM * DDIM];   // w_down [e][k] hi
__device__ __nv_bfloat16 g_wdlo[EDIM * DDIM];
__device__ __nv_bfloat16 g_cbhi[NCODE * EDIM];  // codebook [j][e] hi
__device__ __nv_bfloat16 g_cblo[NCODE * EDIM];
__device__ float g_cnh[NCODE];                  // 0.5*||c_j||^2
__device__ float g_M[NCODE * DDIM];             // codebook @ w_up^T
__device__ float g_lossTok[NTOK];
__device__ int   g_rescue[NTOK];
__device__ int   g_nrescue;

// ---------------------------------------------------------------------------
// mma / ldmatrix helpers (base-arch PTX)
// ---------------------------------------------------------------------------
__device__ __forceinline__ u32 smem_u32(const void* p) {
    u32 a;
    asm("{ .reg .u64 t; cvta.to.shared.u64 t, %1; cvt.u32.u64 %0, t; }" : "=r"(a) : "l"(p));
    return a;
}

__device__ __forceinline__ void ldsm4(u32 addr, u32& r0, u32& r1, u32& r2, u32& r3) {
    asm volatile("ldmatrix.sync.aligned.m8n8.x4.shared.b16 {%0,%1,%2,%3}, [%4];"
                 : "=r"(r0), "=r"(r1), "=r"(r2), "=r"(r3) : "r"(addr));
}
__device__ __forceinline__ void ldsm2(u32 addr, u32& r0, u32& r1) {
    asm volatile("ldmatrix.sync.aligned.m8n8.x2.shared.b16 {%0,%1}, [%2];"
                 : "=r"(r0), "=r"(r1) : "r"(addr));
}
__device__ __forceinline__ void mma16816(float* c, const u32* a, const u32* b) {
    asm volatile(
        "mma.sync.aligned.m16n8k16.row.col.f32.bf16.bf16.f32 "
        "{%0,%1,%2,%3}, {%4,%5,%6,%7}, {%8,%9}, {%0,%1,%2,%3};"
        : "+f"(c[0]), "+f"(c[1]), "+f"(c[2]), "+f"(c[3])
        : "r"(a[0]), "r"(a[1]), "r"(a[2]), "r"(a[3]), "r"(b[0]), "r"(b[1]));
}

__device__ __forceinline__ u32 pack_hi(float a, float b) {
    __nv_bfloat162 t; t.x = __float2bfloat16(a); t.y = __float2bfloat16(b);
    return *(u32*)&t;
}
__device__ __forceinline__ u32 pack_lo(float a, float b) {
    __nv_bfloat162 t;
    t.x = __float2bfloat16(a - __bfloat162float(__float2bfloat16(a)));
    t.y = __float2bfloat16(b - __bfloat162float(__float2bfloat16(b)));
    return *(u32*)&t;
}

// ---------------------------------------------------------------------------
// Merged prep kernel: blocks [0,512) wd split | [512,1536) cb split |
// [1536,1540) cnh | [1540,3588) M. Identical numerics to R13.
// ---------------------------------------------------------------------------
__global__ void k_prep_all(const float* __restrict__ wd, const float* __restrict__ cb,
                           const float* __restrict__ wu) {
    __shared__ float scb[8 * 256];
    __shared__ float swu[32 * 260];
    int b = blockIdx.x, tid = threadIdx.x;
    if (b < 512) {
        int idx = b * 256 + tid;
        float v = wd[idx];
        __nv_bfloat16 hi = __float2bfloat16(v);
        g_wdhi[idx] = hi;
        g_wdlo[idx] = __float2bfloat16(v - __bfloat162float(hi));
    } else if (b < 1536) {
        int idx = (b - 512) * 256 + tid;
        float v = cb[idx];
        __nv_bfloat16 hi = __float2bfloat16(v);
        g_cbhi[idx] = hi;
        g_cblo[idx] = __float2bfloat16(v - __bfloat162float(hi));
    } else if (b < 1540) {
        int j = (b - 1536) * 256 + tid;
        if (j == 0) g_nrescue = 0;
        if (j < NCODE) {
            const float4* r = (const float4*)(cb + (size_t)j * EDIM);
            float s = 0.f;
#pragma unroll 8
            for (int q = 0; q < EDIM / 4; q++) {
                float4 v = r[q];
                s += v.x * v.x + v.y * v.y + v.z * v.z + v.w * v.w;
            }
            g_cnh[j] = 0.5f * s;
        }
    } else {
        int mb = b - 1540;
        int j0 = (mb >> 4) * 8;
        int d0 = (mb & 15) * 32;
#pragma unroll
        for (int r = 0; r < 2; r++) {
            int idx = tid + r * 256;
            int row = idx >> 6, q = (idx & 63) << 2;
            *(float4*)&scb[row * 256 + q] = *(const float4*)&cb[(size_t)(j0 + row) * EDIM + q];
        }
#pragma unroll
        for (int r = 0; r < 8; r++) {
            int idx = tid + r * 256;
            int row = idx >> 6, q = (idx & 63) << 2;
            *(float4*)&swu[row * 260 + q] = *(const float4*)&wu[(size_t)(d0 + row) * EDIM + q];
        }
        __syncthreads();
        int jl = tid >> 5, dl = tid & 31;
        float s = 0.f;
#pragma unroll 16
        for (int e = 0; e < 256; e += 4) {
            float4 a = *(float4*)&scb[jl * 256 + e];
            float4 bq = *(float4*)&swu[dl * 260 + e];
            s += a.x * bq.x + a.y * bq.y + a.z * bq.z + a.w * bq.w;
        }
        g_M[(size_t)(j0 + jl) * DDIM + d0 + dl] = s;
    }
}

// ---------------------------------------------------------------------------
// Main kernel: UNCHANGED from R12/R13 (known-good 586us).
// ---------------------------------------------------------------------------
#define OFF_ZEHI 0
#define OFF_ZELO 33792
#define OFF_P    67584
#define OFF_AZHI (OFF_P)
#define OFF_AZLO (OFF_P + 3072)
#define OFF_BWHI (OFF_P + 6144)
#define OFF_BWLO (OFF_P + 18432)
#define OFF_BHI  (OFF_P)
#define OFF_BLO  (OFF_P + 18432)
#define SM_TOTAL 104448

__global__ __launch_bounds__(256, 2) void vq_mma(
    const float* __restrict__ z, float* __restrict__ out, int write_extra)
{
    extern __shared__ char sm[];
    __shared__ float s_min[8][64];
    __shared__ float s_min2[8][64];
    __shared__ int   s_idx[8][64];
    __shared__ float s_zn[8][64];
    __shared__ int   s_code[64];

    const int tid = threadIdx.x;
    const int w = tid >> 5, lane = tid & 31;
    const int tok0 = blockIdx.x * TILE_M;
    const u32 smb = smem_u32(sm);

    float acc[4][4][4];
#pragma unroll
    for (int m = 0; m < 4; m++)
#pragma unroll
        for (int nt = 0; nt < 4; nt++)
#pragma unroll
            for (int c = 0; c < 4; c++) acc[m][nt][c] = 0.f;

    // ================= Phase 1: z_e = z @ w_down^T ===========================
#pragma unroll 1
    for (int kc = 0; kc < 32; kc++) {
        {
            int row = tid >> 2, c4 = tid & 3;
            float4 v = *(const float4*)&z[(size_t)(tok0 + row) * DDIM + kc * 16 + c4 * 4];
            u32 off = (u32)(row * 24 + c4 * 4) * 2;
            *(uint2*)(sm + OFF_AZHI + off) = make_uint2(pack_hi(v.x, v.y), pack_hi(v.z, v.w));
            *(uint2*)(sm + OFF_AZLO + off) = make_uint2(pack_lo(v.x, v.y), pack_lo(v.z, v.w));
        }
#pragma unroll
        for (int j = 0; j < 2; j++) {
            int idx = tid + j * 256;
            int row = idx >> 1, q = idx & 1;
            u32 doff = (u32)(row * 24 + q * 8) * 2;
            *(uint4*)(sm + OFF_BWHI + doff) = *(const uint4*)&g_wdhi[row * DDIM + kc * 16 + q * 8];
            *(uint4*)(sm + OFF_BWLO + doff) = *(const uint4*)&g_wdlo[row * DDIM + kc * 16 + q * 8];
        }
        __syncthreads();
        {
            u32 bh[4][2], bl[4][2];
#pragma unroll
            for (int nt = 0; nt < 4; nt++) {
                u32 a = (u32)((w * 32 + nt * 8 + (lane & 7)) * 24 + ((lane >> 3) & 1) * 8) * 2;
                ldsm2(smb + OFF_BWHI + a, bh[nt][0], bh[nt][1]);
                ldsm2(smb + OFF_BWLO + a, bl[nt][0], bl[nt][1]);
            }
#pragma unroll
            for (int m = 0; m < 4; m++) {
                u32 ah[4], al[4];
                u32 aA = (u32)((m * 16 + (lane & 15)) * 24 + (lane >> 4) * 8) * 2;
                ldsm4(smb + OFF_AZHI + aA, ah[0], ah[1], ah[2], ah[3]);
                ldsm4(smb + OFF_AZLO + aA, al[0], al[1], al[2], al[3]);
#pragma unroll
                for (int nt = 0; nt < 4; nt++) {
                    mma16816(acc[m][nt], ah, bh[nt]);
                    mma16816(acc[m][nt], al, bh[nt]);
                    mma16816(acc[m][nt], ah, bl[nt]);
                }
            }
        }
        __syncthreads();
    }

    // ---- phase-1 epilogue ----
    {
        float znp[8];
#pragma unroll
        for (int s = 0; s < 8; s++) znp[s] = 0.f;
#pragma unroll
        for (int m = 0; m < 4; m++) {
#pragma unroll
            for (int nt = 0; nt < 4; nt++) {
                float c0 = acc[m][nt][0], c1 = acc[m][nt][1];
                float c2 = acc[m][nt][2], c3 = acc[m][nt][3];
                znp[m * 2]     += c0 * c0 + c1 * c1;
                znp[m * 2 + 1] += c2 * c2 + c3 * c3;
                int e0 = w * 32 + nt * 8 + 2 * (lane & 3);
                int r1 = m * 16 + (lane >> 2);
                u32 o1 = (u32)(r1 * 264 + e0) * 2;
                u32 o2 = (u32)((r1 + 8) * 264 + e0) * 2;
                *(u32*)(sm + OFF_ZEHI + o1) = pack_hi(c0, c1);
                *(u32*)(sm + OFF_ZELO + o1) = pack_lo(c0, c1);
                *(u32*)(sm + OFF_ZEHI + o2) = pack_hi(c2, c3);
                *(u32*)(sm + OFF_ZELO + o2) = pack_lo(c2, c3);
            }
        }
#pragma unroll
        for (int s = 0; s < 8; s++) {
            znp[s] += __shfl_xor_sync(0xffffffffu, znp[s], 1);
            znp[s] += __shfl_xor_sync(0xffffffffu, znp[s], 2);
        }
        if ((lane & 3) == 0) {
#pragma unroll
            for (int m = 0; m < 4; m++) {
                int r1 = m * 16 + (lane >> 2);
                s_zn[w][r1]     = znp[m * 2];
                s_zn[w][r1 + 8] = znp[m * 2 + 1];
            }
        }
    }
    __syncthreads();

    // ================= Phase 2: scores vs 1024 codes =========================
    float minv[8], minv2[8]; int mini[8];
#pragma unroll
    for (int s = 0; s < 8; s++) { minv[s] = 3.4e38f; minv2[s] = 3.4e38f; mini[s] = 0; }

#pragma unroll 1
    for (int jc = 0; jc < 8; jc++) {
        float acc2[4][2][4];
#pragma unroll
        for (int m = 0; m < 4; m++)
#pragma unroll
            for (int nt = 0; nt < 2; nt++)
#pragma unroll
                for (int c = 0; c < 4; c++) acc2[m][nt][c] = 0.f;

#pragma unroll 1
        for (int kc = 0; kc < 4; kc++) {
#pragma unroll
            for (int j = 0; j < 4; j++) {
                int idx = tid + j * 256;
                int row = idx >> 3, q = idx & 7;
                u32 doff = (u32)(row * 72 + q * 8) * 2;
                *(uint4*)(sm + OFF_BHI + doff) =
                    *(const uint4*)&g_cbhi[(size_t)(jc * 128 + row) * EDIM + kc * 64 + q * 8];
                *(uint4*)(sm + OFF_BLO + doff) =
                    *(const uint4*)&g_cblo[(size_t)(jc * 128 + row) * EDIM + kc * 64 + q * 8];
            }
            __syncthreads();
#pragma unroll
            for (int ks = 0; ks < 4; ks++) {
                u32 bh[2][2], bl[2][2];
#pragma unroll
                for (int nt = 0; nt < 2; nt++) {
                    u32 a = (u32)((w * 16 + nt * 8 + (lane & 7)) * 72 + ks * 16 + ((lane >> 3) & 1) * 8) * 2;
                    ldsm2(smb + OFF_BHI + a, bh[nt][0], bh[nt][1]);
                    ldsm2(smb + OFF_BLO + a, bl[nt][0], bl[nt][1]);
                }
#pragma unroll
                for (int m = 0; m < 4; m++) {
                    u32 ah[4], al[4];
                    u32 aA = (u32)((m * 16 + (lane & 15)) * 264 + kc * 64 + ks * 16 + (lane >> 4) * 8) * 2;
                    ldsm4(smb + OFF_ZEHI + aA, ah[0], ah[1], ah[2], ah[3]);
                    ldsm4(smb + OFF_ZELO + aA, al[0], al[1], al[2], al[3]);
#pragma unroll
                    for (int nt = 0; nt < 2; nt++) {
                        mma16816(acc2[m][nt], ah, bh[nt]);
                        mma16816(acc2[m][nt], al, bh[nt]);
                        mma16816(acc2[m][nt], ah, bl[nt]);
                    }
                }
            }
            __syncthreads();
        }
        float cn[4];
#pragma unroll
        for (int nt = 0; nt < 2; nt++) {
            int jb = jc * 128 + w * 16 + nt * 8 + 2 * (lane & 3);
            cn[nt * 2]     = __ldg(&g_cnh[jb]);
            cn[nt * 2 + 1] = __ldg(&g_cnh[jb + 1]);
        }
#pragma unroll
        for (int m = 0; m < 4; m++) {
#pragma unroll
            for (int nt = 0; nt < 2; nt++) {
#pragma unroll
                for (int c = 0; c < 4; c++) {
                    float s = cn[nt * 2 + (c & 1)] - acc2[m][nt][c];
                    int code = jc * 128 + w * 16 + nt * 8 + 2 * (lane & 3) + (c & 1);
                    int slot = m * 2 + (c >> 1);
                    if (s < minv[slot]) { minv2[slot] = minv[slot]; minv[slot] = s; mini[slot] = code; }
                    else if (s < minv2[slot]) { minv2[slot] = s; }
                }
            }
        }
    }

#pragma unroll
    for (int s = 0; s < 8; s++) {
#pragma unroll
        for (int off = 1; off <= 2; off <<= 1) {
            float ov  = __shfl_xor_sync(0xffffffffu, minv[s], off);
            float ov2 = __shfl_xor_sync(0xffffffffu, minv2[s], off);
            int   oi  = __shfl_xor_sync(0xffffffffu, mini[s], off);
            float nv2 = fminf(fmaxf(minv[s], ov), fminf(minv2[s], ov2));
            if (ov < minv[s] || (ov == minv[s] && oi < mini[s])) { minv[s] = ov; mini[s] = oi; }
            minv2[s] = nv2;
        }
    }
    if ((lane & 3) == 0) {
#pragma unroll
        for (int m = 0; m < 4; m++) {
            int r1 = m * 16 + (lane >> 2);
            s_min[w][r1] = minv[m * 2];      s_min2[w][r1] = minv2[m * 2];      s_idx[w][r1] = mini[m * 2];
            s_min[w][r1 + 8] = minv[m * 2 + 1]; s_min2[w][r1 + 8] = minv2[m * 2 + 1]; s_idx[w][r1 + 8] = mini[m * 2 + 1];
        }
    }
    __syncthreads();

    if (tid < 64) {
        float v = s_min[0][tid], v2 = s_min2[0][tid], zn = s_zn[0][tid];
        int id = s_idx[0][tid];
#pragma unroll
        for (int ww = 1; ww < 8; ww++) {
            float ov = s_min[ww][tid], ov2 = s_min2[ww][tid];
            int oi = s_idx[ww][tid];
            float nv2 = fminf(fmaxf(v, ov), fminf(v2, ov2));
            if (ov < v || (ov == v && oi < id)) { v = ov; id = oi; }
            v2 = nv2;
            zn += s_zn[ww][tid];
        }
        int tok = tok0 + tid;
        g_lossTok[tok] = 2.f * v + zn;
        if (write_extra) out[OFF_CODE + tok] = (float)id;
        s_code[tid] = id;
        if (v2 - v < TAU) {
            int slot = atomicAdd(&g_nrescue, 1);
            g_rescue[slot] = tok;
        }
    }
    __syncthreads();

#pragma unroll 1
    for (int j = 0; j < 32; j++) {
        int idx = tid + j * 256;
        int row = idx >> 7, q = idx & 127;
        int c = s_code[row];
        float4 vv = *(const float4*)&g_M[(size_t)c * DDIM + q * 4];
        *(float4*)&out[(size_t)(tok0 + row) * DDIM + q * 4] = vv;
    }
}

// ---------------------------------------------------------------------------
// Rescue v3: same bit-exact accumulation chains as R11/R13 (each dot/s0/s1
// accumulates over ascending kb, ascending q; compares in ascending c), but
// restructured: kb outermost, ze chunk cached in registers, all 8 code-chunk
// accumulators live simultaneously. RB=4 for 2x block parallelism.
// ---------------------------------------------------------------------------
#define RB 4
__global__ __launch_bounds__(128) void k_rescue(
    const float* __restrict__ z, const float* __restrict__ cb,
    const float* __restrict__ wd, float* __restrict__ out, int write_extra)
{
    __shared__ float zr[RB][512];
    __shared__ float ze[RB][256];
    __shared__ float rbd[RB][128];
    __shared__ int   rbi[RB][128];
    __shared__ float rzn[RB][128];
    __shared__ int   stok[RB];

    int tid = threadIdx.x;
    int n = g_nrescue;
    if (n <= 0) return;
    for (int base = blockIdx.x * RB; base < n; base += gridDim.x * RB) {
        if (tid < RB) {
            int idx = base + tid; if (idx > n - 1) idx = n - 1;   // pad w/ last token
            stok[tid] = g_rescue[idx];
        }
        __syncthreads();
#pragma unroll
        for (int t = 0; t < RB; t++)
            ((float4*)zr[t])[tid] = ((const float4*)&z[(size_t)stok[t] * DDIM])[tid];
        __syncthreads();

        // ---- exact z_e: thread -> columns (2*tid, 2*tid+1), ascending-k chain
        {
            int e0 = tid * 2;
            const float* w0 = wd + (size_t)e0 * DDIM;
            const float* w1 = w0 + DDIM;
            float s0[RB], s1[RB];
#pragma unroll
            for (int t = 0; t < RB; t++) { s0[t] = 0.f; s1[t] = 0.f; }
#pragma unroll 2
            for (int kb = 0; kb < 512; kb += 8) {
                float a0[8], a1[8];
#pragma unroll
                for (int q = 0; q < 8; q++) { a0[q] = w0[kb + q]; a1[q] = w1[kb + q]; }
                float zreg[RB][8];
#pragma unroll
                for (int t = 0; t < RB; t++)
#pragma unroll
                    for (int q = 0; q < 8; q++) zreg[t][q] = zr[t][kb + q];
#pragma unroll
                for (int t = 0; t < RB; t++) {
#pragma unroll
                    for (int q = 0; q < 8; q++) {
                        s0[t] = __fmaf_rn(zreg[t][q], a0[q], s0[t]);
                        s1[t] = __fmaf_rn(zreg[t][q], a1[q], s1[t]);
                    }
                }
            }
#pragma unroll
            for (int t = 0; t < RB; t++) { ze[t][e0] = s0[t]; ze[t][e0 + 1] = s1[t]; }
        }
        __syncthreads();

        // ---- exact scores: thread owns codes {c*128+tid}; dot chains ascending
        // kb,q per code; compares ascending c (identical result to R13).
        {
            float dot[8][RB];
#pragma unroll
            for (int c = 0; c < 8; c++)
#pragma unroll
                for (int t = 0; t < RB; t++) dot[c][t] = 0.f;
            float znp[RB];
#pragma unroll
            for (int t = 0; t < RB; t++) {
                float a = ze[t][2 * tid], b = ze[t][2 * tid + 1];
                znp[t] = a * a + b * b;
            }
#pragma unroll 2
            for (int kb = 0; kb < 256; kb += 8) {
                float zreg[RB][8];
#pragma unroll
                for (int t = 0; t < RB; t++)
#pragma unroll
                    for (int q = 0; q < 8; q++) zreg[t][q] = ze[t][kb + q];
#pragma unroll
                for (int c = 0; c < 8; c++) {
                    const float* cr = cb + (size_t)(c * 128 + tid) * EDIM;
                    float c8[8];
#pragma unroll
                    for (int q = 0; q < 8; q++) c8[q] = cr[kb + q];
#pragma unroll
                    for (int t = 0; t < RB; t++)
#pragma unroll
                        for (int q = 0; q < 8; q++)
                            dot[c][t] = __fmaf_rn(zreg[t][q], c8[q], dot[c][t]);
                }
            }
            float best[RB]; int bidx[RB];
#pragma unroll
            for (int t = 0; t < RB; t++) { best[t] = 3.4e38f; bidx[t] = 0; }
#pragma unroll
            for (int c = 0; c < 8; c++) {
                int j = c * 128 + tid;
                float cn = __ldg(&g_cnh[j]);
#pragma unroll
                for (int t = 0; t < RB; t++) {
                    float s = cn - dot[c][t];
                    if (s < best[t]) { best[t] = s; bidx[t] = j; }
                }
            }
#pragma unroll
            for (int t = 0; t < RB; t++) {
                rbd[t][tid] = best[t]; rbi[t][tid] = bidx[t]; rzn[t][tid] = znp[t];
            }
        }
        __syncthreads();
        for (int off = 64; off > 0; off >>= 1) {
            if (tid < off) {
#pragma unroll
                for (int t = 0; t < RB; t++) {
                    float ov = rbd[t][tid + off]; int oi = rbi[t][tid + off];
                    if (ov < rbd[t][tid] || (ov == rbd[t][tid] && oi < rbi[t][tid])) {
                        rbd[t][tid] = ov; rbi[t][tid] = oi;
                    }
                    rzn[t][tid] += rzn[t][tid + off];
                }
            }
            __syncthreads();
        }
#pragma unroll
        for (int t = 0; t < RB; t++) {
            int tok = stok[t]; int cw = rbi[t][0];
            ((float4*)&out[(size_t)tok * DDIM])[tid] = ((const float4*)&g_M[(size_t)cw * DDIM])[tid];
            if (tid == 0) {
                g_lossTok[tok] = 2.f * rbd[t][0] + rzn[t][0];
                if (write_extra) out[OFF_CODE + tok] = (float)cw;
            }
        }
        __syncthreads();
    }
}

// ---------------------------------------------------------------------------
__global__ void k_finalize(float* __restrict__ out) {
    __shared__ float p[128];
    int b = blockIdx.x, tid = threadIdx.x;
    float s = 0.f;
    for (int q = 0; q < 32; q++) s += g_lossTok[b * TLEN + tid * 32 + q];
    p[tid] = s;
    __syncthreads();
    for (int off = 64; off > 0; off >>= 1) {
        if (tid < off) p[tid] += p[tid + off];
        __syncthreads();
    }
    if (tid == 0) {
        float loss = p[0] * (1.0f / ((float)TLEN * (float)EDIM));
        out[OFF_L1 + b] = loss;
        out[OFF_L2 + b] = loss;
    }
}

// ---------------------------------------------------------------------------
extern "C" void kernel_launch(void* const* d_in, const int* in_sizes, int n_in,
                              void* d_out, int out_size) {
    const float* z  = (const float*)d_in[0];
    const float* cb = (const float*)d_in[1];
    const float* wd = (const float*)d_in[2];
    const float* wu = (const float*)d_in[3];
    float* out = (float*)d_out;

    int write_extra = ((size_t)out_size >= OUT_FULL) ? 1 : 0;

    cudaFuncSetAttribute(vq_mma, cudaFuncAttributeMaxDynamicSharedMemorySize, SM_TOTAL);

    k_prep_all<<<3588, 256>>>(wd, cb, wu);
    vq_mma<<<NTILES, 256, SM_TOTAL>>>(z, out, write_extra);
    k_rescue<<<1024, 128>>>(z, cb, wd, out, write_extra);
    k_finalize<<<BATCH, 128>>>(out);
}